// round 12
// baseline (speedup 1.0000x reference)
#include <cuda_runtime.h>
#include <cuda_bf16.h>
#include <math.h>
#include <cstdint>

#define B_     4
#define CIN_   256
#define N_     4096
#define HEADS_ 4
#define DH_    32
#define HID_   128
#define OQKV_  384
#define TPITCH 80u
#define TILEB  10240

// Scratch (allocation-free rule: __device__ globals)
__device__ float g_qkv[B_ * OQKV_ * N_];    // [b][o][n]: q 0..127, k 128..255, v 256..383
__device__ float g_scale[B_ * HID_];        // 10 / (||q_d|| ||k_d||)
__device__ float g_vsum[B_ * HID_];         // sum_j v[d][j]
__device__ __align__(16) unsigned char g_pack[16 * 64 * TILEB];  // attn K'/V bf16 tiles
// split-precision operands for the projection GEMMs
__device__ __align__(16) __nv_bfloat16 g_xh[B_ * CIN_ * N_];
__device__ __align__(16) __nv_bfloat16 g_xl[B_ * CIN_ * N_];
__device__ __align__(16) __nv_bfloat16 g_oh[B_ * HID_ * N_];   // attn out hi (written by attn)
__device__ __align__(16) __nv_bfloat16 g_ol[B_ * HID_ * N_];   // attn out lo
// W hi/lo packed into cp.async-ready 64m x 32k tiles (80B pitch rows, hi|lo)
__device__ __align__(16) unsigned char g_wp1[6 * 8 * TILEB];   // w_qkv: 384x256
__device__ __align__(16) unsigned char g_wp2[4 * 4 * TILEB];   // w_out: 256x128

// ---------------------------------------------------------------------------
// helpers
// ---------------------------------------------------------------------------
__device__ __forceinline__ uint32_t smem_to_u32(const void* p) {
    uint32_t a;
    asm("{ .reg .u64 t; cvta.to.shared.u64 t, %1; cvt.u32.u64 %0, t; }" : "=r"(a) : "l"(p));
    return a;
}

__device__ __forceinline__ void mma_bf16(float c[4],
                                         uint32_t a0, uint32_t a1, uint32_t a2, uint32_t a3,
                                         uint32_t b0, uint32_t b1) {
    asm volatile(
        "mma.sync.aligned.m16n8k16.row.col.f32.bf16.bf16.f32 "
        "{%0,%1,%2,%3}, {%4,%5,%6,%7}, {%8,%9}, {%0,%1,%2,%3};"
        : "+f"(c[0]), "+f"(c[1]), "+f"(c[2]), "+f"(c[3])
        : "r"(a0), "r"(a1), "r"(a2), "r"(a3), "r"(b0), "r"(b1));
}

// D = A.B + 0 : separate D/C, C = hoisted zero regs
__device__ __forceinline__ void mma_bf16_zc(float c[4],
                                            uint32_t a0, uint32_t a1, uint32_t a2, uint32_t a3,
                                            uint32_t b0, uint32_t b1) {
    asm volatile(
        "mma.sync.aligned.m16n8k16.row.col.f32.bf16.bf16.f32 "
        "{%0,%1,%2,%3}, {%4,%5,%6,%7}, {%8,%9}, {%10,%11,%12,%13};"
        : "=f"(c[0]), "=f"(c[1]), "=f"(c[2]), "=f"(c[3])
        : "r"(a0), "r"(a1), "r"(a2), "r"(a3), "r"(b0), "r"(b1),
          "f"(0.0f), "f"(0.0f), "f"(0.0f), "f"(0.0f));
}

__device__ __forceinline__ void ldsm4(uint32_t& r0, uint32_t& r1, uint32_t& r2, uint32_t& r3,
                                      uint32_t addr) {
    asm volatile("ldmatrix.sync.aligned.m8n8.x4.shared.b16 {%0,%1,%2,%3}, [%4];"
                 : "=r"(r0), "=r"(r1), "=r"(r2), "=r"(r3) : "r"(addr));
}
__device__ __forceinline__ void ldsm4t(uint32_t& r0, uint32_t& r1, uint32_t& r2, uint32_t& r3,
                                       uint32_t addr) {
    asm volatile("ldmatrix.sync.aligned.m8n8.x4.trans.shared.b16 {%0,%1,%2,%3}, [%4];"
                 : "=r"(r0), "=r"(r1), "=r"(r2), "=r"(r3) : "r"(addr));
}

__device__ __forceinline__ uint32_t packbf2(float lo, float hi) {
    __nv_bfloat162 p = __floats2bfloat162_rn(lo, hi);
    return *reinterpret_cast<uint32_t*>(&p);
}
__device__ __forceinline__ uint32_t bf2u(__nv_bfloat162 p) {
    return *reinterpret_cast<uint32_t*>(&p);
}

__device__ __forceinline__ void cp_async16(uint32_t s, const void* g) {
    asm volatile("cp.async.cg.shared.global [%0], [%1], 16;" :: "r"(s), "l"(g));
}

// ---------------------------------------------------------------------------
// convert_split: fp32 -> (bf16 hi, bf16 lo = x - hi), 4 elems/thread
// ---------------------------------------------------------------------------
__global__ void __launch_bounds__(256) convert_split(
    const float* __restrict__ src, __nv_bfloat16* __restrict__ hi,
    __nv_bfloat16* __restrict__ lo, int n4)
{
    int idx = blockIdx.x * 256 + threadIdx.x;
    if (idx >= n4) return;
    float4 f = reinterpret_cast<const float4*>(src)[idx];
    __nv_bfloat16 h0 = __float2bfloat16_rn(f.x);
    __nv_bfloat16 h1 = __float2bfloat16_rn(f.y);
    __nv_bfloat16 h2 = __float2bfloat16_rn(f.z);
    __nv_bfloat16 h3 = __float2bfloat16_rn(f.w);
    uint2 hw, lw;
    __nv_bfloat162 p01; p01.x = h0; p01.y = h1;
    __nv_bfloat162 p23; p23.x = h2; p23.y = h3;
    hw.x = bf2u(p01); hw.y = bf2u(p23);
    lw.x = packbf2(f.x - __bfloat162float(h0), f.y - __bfloat162float(h1));
    lw.y = packbf2(f.z - __bfloat162float(h2), f.w - __bfloat162float(h3));
    reinterpret_cast<uint2*>(hi)[idx] = hw;
    reinterpret_cast<uint2*>(lo)[idx] = lw;
}

// ---------------------------------------------------------------------------
// convert_w: W fp32 [M][K] -> packed tiles [mt][s][ hi 64x80B | lo 64x80B ]
// ---------------------------------------------------------------------------
__global__ void __launch_bounds__(256) convert_w(
    const float* __restrict__ W, unsigned char* __restrict__ dst, int M, int K)
{
    const int mt = blockIdx.x, s = blockIdx.y;
    const int m  = threadIdx.x & 63;
    const int kg = (threadIdx.x >> 6) * 8;
    unsigned char* base = dst + ((size_t)mt * (K >> 5) + s) * TILEB;
    const float* wrow = W + (size_t)(mt * 64 + m) * K + s * 32 + kg;

    #pragma unroll
    for (int p = 0; p < 4; p++) {
        float w0 = wrow[2 * p], w1 = wrow[2 * p + 1];
        __nv_bfloat16 h0 = __float2bfloat16_rn(w0);
        __nv_bfloat16 h1 = __float2bfloat16_rn(w1);
        __nv_bfloat162 ph; ph.x = h0; ph.y = h1;
        int k = kg + 2 * p;
        uint32_t off = (uint32_t)m * TPITCH + (uint32_t)((k >> 3) * 16 + (k & 7) * 2);
        *reinterpret_cast<uint32_t*>(base + off) = bf2u(ph);
        *reinterpret_cast<uint32_t*>(base + 5120 + off) =
            packbf2(w0 - __bfloat162float(h0), w1 - __bfloat162float(h1));
    }
}

// ---------------------------------------------------------------------------
// Split-bf16 tensor-core GEMM: out[b][m][n] = sum_k W[m][k] X[b][k][n] (+bias)
// m-tiles >= mt3: 3-pass (Xh.Wh + Xl.Wh + Xh.Wl). m-tiles < mt3: single-pass
// Xh.Wh — valid for q/k rows (self-consistent l2 normalization).
// ---------------------------------------------------------------------------
__global__ void __launch_bounds__(256) gemm_mma(
    const __nv_bfloat16* __restrict__ Xh, const __nv_bfloat16* __restrict__ Xl,
    const unsigned char* __restrict__ Wp, const float* __restrict__ bias,
    float* __restrict__ out, int M, int K, int mt3)
{
    __shared__ __align__(16) unsigned char smem[2][18432];

    const int tid = threadIdx.x, lane = tid & 31, w = tid >> 5;
    const int wn = w & 3, wm = w >> 2;
    const int g = lane >> 2, tg = lane & 3;
    const int n0 = blockIdx.x * 64, mt = blockIdx.y, b = blockIdx.z;
    const int nstages = K >> 5;
    const bool full = (mt >= mt3);

    const __nv_bfloat16* xh = Xh + (size_t)b * K * N_ + n0;
    const __nv_bfloat16* xl = Xl + (size_t)b * K * N_ + n0;
    const unsigned char* wp = Wp + (size_t)mt * nstages * TILEB;

    const int ck = tid >> 3, cc = tid & 7;
    const uint32_t xdst = (uint32_t)(ck * 128 + ((cc ^ (ck & 7)) * 16));

    auto issue = [&](int s) {
        uint32_t dst = smem_to_u32(smem[s & 1]);
        const char* sh = (const char*)(xh + (size_t)(s * 32 + ck) * N_) + cc * 16;
        cp_async16(dst + xdst, sh);
        if (full) {
            const char* sl = (const char*)(xl + (size_t)(s * 32 + ck) * N_) + cc * 16;
            cp_async16(dst + 4096 + xdst, sl);
        }
        const unsigned char* ws = wp + (size_t)s * TILEB;
        cp_async16(dst + 8192 + tid * 16, ws + tid * 16);
        cp_async16(dst + 8192 + (tid + 256) * 16, ws + (tid + 256) * 16);
        if (full && tid < 128)
            cp_async16(dst + 8192 + (tid + 512) * 16, ws + (tid + 512) * 16);
        asm volatile("cp.async.commit_group;" ::: "memory");
    };

    float acc[4][4] = {};

    issue(0);
    for (int s = 0; s < nstages; s++) {
        if (s + 1 < nstages) {
            issue(s + 1);
            asm volatile("cp.async.wait_group 1;" ::: "memory");
        } else {
            asm volatile("cp.async.wait_group 0;" ::: "memory");
        }
        __syncthreads();

        const uint32_t smX = smem_to_u32(smem[s & 1]);
        const uint32_t smW = smX + 8192;

        uint32_t Ah[2][4], Al[2][4];
        const int arow = ((lane & 16) >> 1) + (lane & 7);
        const int alog = wn * 2 + ((lane >> 3) & 1);
        #pragma unroll
        for (int ks = 0; ks < 2; ks++) {
            int kr = ks * 16 + arow;
            uint32_t aoff = (uint32_t)(kr * 128 + ((alog ^ (kr & 7)) * 16));
            ldsm4t(Ah[ks][0], Ah[ks][1], Ah[ks][2], Ah[ks][3], smX + aoff);
            if (full)
                ldsm4t(Al[ks][0], Al[ks][1], Al[ks][2], Al[ks][3], smX + 4096 + aoff);
        }

        #pragma unroll
        for (int mb = 0; mb < 4; mb++) {
            uint32_t waddr = smW + (uint32_t)((wm * 32 + mb * 8 + (lane & 7)) * TPITCH
                                              + (lane >> 3) * 16);
            uint32_t bh0, bh1, bh2, bh3;
            ldsm4(bh0, bh1, bh2, bh3, waddr);
            mma_bf16(acc[mb], Ah[0][0], Ah[0][1], Ah[0][2], Ah[0][3], bh0, bh1);
            mma_bf16(acc[mb], Ah[1][0], Ah[1][1], Ah[1][2], Ah[1][3], bh2, bh3);
            if (full) {
                uint32_t bl0, bl1, bl2, bl3;
                ldsm4(bl0, bl1, bl2, bl3, waddr + 5120);
                mma_bf16(acc[mb], Al[0][0], Al[0][1], Al[0][2], Al[0][3], bh0, bh1);
                mma_bf16(acc[mb], Al[1][0], Al[1][1], Al[1][2], Al[1][3], bh2, bh3);
                mma_bf16(acc[mb], Ah[0][0], Ah[0][1], Ah[0][2], Ah[0][3], bl0, bl1);
                mma_bf16(acc[mb], Ah[1][0], Ah[1][1], Ah[1][2], Ah[1][3], bl2, bl3);
            }
        }
        __syncthreads();
    }

    const int nA = n0 + wn * 16 + g, nB = nA + 8;
    #pragma unroll
    for (int mb = 0; mb < 4; mb++) {
        int m = mt * 64 + wm * 32 + mb * 8 + 2 * tg;
        float bv0 = bias ? bias[m] : 0.0f;
        float bv1 = bias ? bias[m + 1] : 0.0f;
        float* o0 = out + ((size_t)b * M + m) * N_;
        float* o1 = o0 + N_;
        o0[nA] = acc[mb][0] + bv0;
        o1[nA] = acc[mb][1] + bv1;
        o0[nB] = acc[mb][2] + bv0;
        o1[nB] = acc[mb][3] + bv1;
    }
}

// ---------------------------------------------------------------------------
// Per (b,hd): q,k row norms (-> folded scale) and v row sum.
// ---------------------------------------------------------------------------
__global__ void __launch_bounds__(256) norm_kernel()
{
    const int idx = blockIdx.x;
    const int b  = idx >> 7;
    const int hd = idx & 127;
    const float* q = g_qkv + ((size_t)(b * OQKV_ + hd)) * N_;
    const float* k = q + (size_t)HID_ * N_;
    const float* v = q + (size_t)(2 * HID_) * N_;

    float sq = 0.f, sk = 0.f, sv = 0.f;
    for (int i = threadIdx.x; i < N_; i += 256) {
        float a = q[i]; sq += a * a;
        float c = k[i]; sk += c * c;
        sv += v[i];
    }
    __shared__ float rq[256], rk[256], rv[256];
    rq[threadIdx.x] = sq; rk[threadIdx.x] = sk; rv[threadIdx.x] = sv;
    __syncthreads();
    for (int s = 128; s > 0; s >>= 1) {
        if (threadIdx.x < s) {
            rq[threadIdx.x] += rq[threadIdx.x + s];
            rk[threadIdx.x] += rk[threadIdx.x + s];
            rv[threadIdx.x] += rv[threadIdx.x + s];
        }
        __syncthreads();
    }
    if (threadIdx.x == 0) {
        float nq = fmaxf(sqrtf(rq[0]), 1e-12f);
        float nk = fmaxf(sqrtf(rk[0]), 1e-12f);
        g_scale[idx] = 10.0f / (nq * nk);
        g_vsum[idx]  = rv[0];
    }
}

// ---------------------------------------------------------------------------
// Pack K' (k * folded scale) and V into bf16 LDSM-ready tiles.
// ---------------------------------------------------------------------------
__global__ void __launch_bounds__(256) pack_kernel()
{
    const int bh = blockIdx.y, ti = blockIdx.x;
    const int b = bh >> 2, h = bh & 3;
    const float* kb = g_qkv + ((size_t)(b * OQKV_) + HID_ + h * DH_) * N_;
    const float* vb = kb + (size_t)HID_ * N_;

    const int j  = threadIdx.x & 63;
    const int dg = threadIdx.x >> 6;
    const int jt = ti * 64;
    unsigned char* out = g_pack + ((size_t)bh * 64 + ti) * TILEB;

    uint32_t kw[4], vw[4];
    #pragma unroll
    for (int p = 0; p < 4; p++) {
        int d = dg * 8 + 2 * p;
        float c0 = g_scale[bh * DH_ + d];
        float c1 = g_scale[bh * DH_ + d + 1];
        float k0 = kb[(size_t)d * N_ + jt + j];
        float k1 = kb[(size_t)(d + 1) * N_ + jt + j];
        kw[p] = packbf2(k0 * c0, k1 * c1);
        vw[p] = packbf2(vb[(size_t)d * N_ + jt + j], vb[(size_t)(d + 1) * N_ + jt + j]);
    }
    *(uint4*)(out + j * TPITCH + dg * 16)        = make_uint4(kw[0], kw[1], kw[2], kw[3]);
    *(uint4*)(out + 5120 + j * TPITCH + dg * 16) = make_uint4(vw[0], vw[1], vw[2], vw[3]);

    if (threadIdx.x < 64) {
        *(uint4*)(out + threadIdx.x * TPITCH + 64) = make_uint4(0u, 0u, 0u, 0u);
    } else if (threadIdx.x < 128) {
        int jj = threadIdx.x - 64;  // V pad: d=32 column of ones (lsum via MMA)
        *(uint4*)(out + 5120 + jj * TPITCH + 64) = make_uint4(0x00003F80u, 0u, 0u, 0u);
    }
}

// ---------------------------------------------------------------------------
// bf16 mma.sync flash attention — 256-query CTAs, 3 CTAs/SM experiment.
// (256,3) caps regs at 85 (24 warps/SM = 6/SMSP); ~15-20 reg spill expected,
// landing on least-used qa fragments (L1-resident, warp-coalesced). Tests the
// latency-bound model: more warps to fill tensor pipe during epilogues.
// ---------------------------------------------------------------------------
__global__ void __launch_bounds__(256, 3) attn_mma_kernel()
{
    __shared__ __align__(16) unsigned char sbuf[4][TILEB];  // 40 KB

    const int tid  = threadIdx.x;
    const int lane = tid & 31;
    const int w    = tid >> 5;
    const int g    = lane >> 2;
    const int tg   = lane & 3;

    const int bh = blockIdx.y;
    const int b = bh >> 2, h = bh & 3;
    const int i0 = blockIdx.x * 256 + w * 32;   // warp owns 32 query rows

    const float* qb = g_qkv + ((size_t)(b * OQKV_) + h * DH_) * N_;
    const unsigned char* pk = g_pack + (size_t)bh * 64 * TILEB;

    // Q fragments: 2 m-blocks x 2 k-steps x 4
    uint32_t qa[2][2][4];
    #pragma unroll
    for (int m = 0; m < 2; m++) {
        #pragma unroll
        for (int ks = 0; ks < 2; ks++) {
            #pragma unroll
            for (int rr = 0; rr < 4; rr++) {
                int r = i0 + m * 16 + g + ((rr & 1) ? 8 : 0);
                int d = ks * 16 + 2 * tg + ((rr >> 1) ? 8 : 0);
                qa[m][ks][rr] = packbf2(qb[(size_t)d * N_ + r], qb[(size_t)(d + 1) * N_ + r]);
            }
        }
    }

    const __nv_bfloat162 C5  = __float2bfloat162_rn(0.5f);
    const __nv_bfloat162 ONE = __float2bfloat162_rn(1.0f);

    auto issue = [&](int ti) {
        const unsigned char* src = pk + (size_t)ti * TILEB;
        uint32_t dst = smem_to_u32(sbuf[ti & 3]);
        cp_async16(dst + tid * 16, src + tid * 16);
        cp_async16(dst + (tid + 256) * 16, src + (tid + 256) * 16);
        if (tid < 128) cp_async16(dst + (tid + 512) * 16, src + (tid + 512) * 16);
        asm volatile("cp.async.commit_group;" ::: "memory");
    };

    float oacc[2][5][4] = {};

    issue(0); issue(1); issue(2);

    for (int ti = 0; ti < 64; ti++) {
        asm volatile("cp.async.wait_group 2;" ::: "memory");
        __syncthreads();
        if (ti + 3 < 64) issue(ti + 3);   // buf consumed at ti-1, safe post-sync

        const uint32_t smK = smem_to_u32(sbuf[ti & 3]);
        const uint32_t smV = smK + 5120;

        #pragma unroll
        for (int hf = 0; hf < 2; hf++) {
            // S + epilogue per n-block: one K ldsm serves BOTH m-blocks
            uint32_t pa[2][2][4];   // [m][pair][frag]
            #pragma unroll
            for (int q4 = 0; q4 < 4; q4++) {
                uint32_t r0, r1, r2, r3;
                uint32_t jrow = (uint32_t)((hf * 4 + q4) * 8 + (lane & 7));
                ldsm4(r0, r1, r2, r3, smK + jrow * TPITCH + (uint32_t)(lane >> 3) * 16u);
                #pragma unroll
                for (int m = 0; m < 2; m++) {
                    float sc[4];
                    mma_bf16_zc(sc, qa[m][0][0], qa[m][0][1], qa[m][0][2], qa[m][0][3], r0, r1);
                    mma_bf16  (sc, qa[m][1][0], qa[m][1][1], qa[m][1][2], qa[m][1][3], r2, r3);
                    // delta = s * (1 + s/2)
                    __nv_bfloat162 s01 = __floats2bfloat162_rn(sc[0], sc[1]);
                    __nv_bfloat162 s23 = __floats2bfloat162_rn(sc[2], sc[3]);
                    __nv_bfloat162 t01 = __hfma2(s01, C5, ONE);
                    __nv_bfloat162 t23 = __hfma2(s23, C5, ONE);
                    pa[m][q4 >> 1][(q4 & 1) * 2 + 0] = bf2u(__hmul2(s01, t01));
                    pa[m][q4 >> 1][(q4 & 1) * 2 + 1] = bf2u(__hmul2(s23, t23));
                }
            }

            // PV: one V ldsm serves 2 m-blocks x 2 k-steps = 4 MMAs
            #pragma unroll
            for (int nbd = 0; nbd < 5; nbd++) {
                uint32_t v0, v1, v2, v3;
                ldsm4t(v0, v1, v2, v3,
                       smV + (uint32_t)(hf * 32 + lane) * TPITCH + (uint32_t)nbd * 16u);
                #pragma unroll
                for (int m = 0; m < 2; m++) {
                    mma_bf16(oacc[m][nbd], pa[m][0][0], pa[m][0][1], pa[m][0][2], pa[m][0][3], v0, v1);
                    mma_bf16(oacc[m][nbd], pa[m][1][0], pa[m][1][1], pa[m][1][2], pa[m][1][3], v2, v3);
                }
            }
        }
    }

    // per m-block: lsum in OUT col 32 (block 4, col 0) owned by tg=0 lanes
    const int chan0 = b * HID_ + h * DH_;
    #pragma unroll
    for (int m = 0; m < 2; m++) {
        float lA = __shfl_sync(0xffffffffu, oacc[m][4][0], lane & ~3);
        float lB = __shfl_sync(0xffffffffu, oacc[m][4][2], lane & ~3);
        const float rA = 1.0f / (4096.0f + lA);
        const float rB = 1.0f / (4096.0f + lB);
        const int iA = i0 + m * 16 + g, iB = iA + 8;
        #pragma unroll
        for (int nbd = 0; nbd < 4; nbd++) {
            int d0 = nbd * 8 + 2 * tg;
            float vs0 = g_vsum[chan0 + d0];
            float vs1 = g_vsum[chan0 + d0 + 1];
            float o00 = (vs0 + oacc[m][nbd][0]) * rA;
            float o10 = (vs1 + oacc[m][nbd][1]) * rA;
            float o01 = (vs0 + oacc[m][nbd][2]) * rB;
            float o11 = (vs1 + oacc[m][nbd][3]) * rB;
            size_t p0 = (size_t)(chan0 + d0) * N_;
            size_t p1 = p0 + N_;
            __nv_bfloat16 hh;
            hh = __float2bfloat16_rn(o00); g_oh[p0 + iA] = hh;
            g_ol[p0 + iA] = __float2bfloat16_rn(o00 - __bfloat162float(hh));
            hh = __float2bfloat16_rn(o10); g_oh[p1 + iA] = hh;
            g_ol[p1 + iA] = __float2bfloat16_rn(o10 - __bfloat162float(hh));
            hh = __float2bfloat16_rn(o01); g_oh[p0 + iB] = hh;
            g_ol[p0 + iB] = __float2bfloat16_rn(o01 - __bfloat162float(hh));
            hh = __float2bfloat16_rn(o11); g_oh[p1 + iB] = hh;
            g_ol[p1 + iB] = __float2bfloat16_rn(o11 - __bfloat162float(hh));
        }
    }
}

// ---------------------------------------------------------------------------
extern "C" void kernel_launch(void* const* d_in, const int* in_sizes, int n_in,
                              void* d_out, int out_size)
{
    (void)in_sizes; (void)n_in; (void)out_size;
    const float* x     = (const float*)d_in[0];
    const float* w_qkv = (const float*)d_in[1];
    const float* w_out = (const float*)d_in[2];
    const float* b_out = (const float*)d_in[3];
    float* y = (float*)d_out;

    float *qkv_p;
    __nv_bfloat16 *xh_p, *xl_p, *oh_p, *ol_p;
    unsigned char *wp1_p, *wp2_p;
    cudaGetSymbolAddress((void**)&qkv_p,  g_qkv);
    cudaGetSymbolAddress((void**)&xh_p,   g_xh);
    cudaGetSymbolAddress((void**)&xl_p,   g_xl);
    cudaGetSymbolAddress((void**)&oh_p,   g_oh);
    cudaGetSymbolAddress((void**)&ol_p,   g_ol);
    cudaGetSymbolAddress((void**)&wp1_p,  g_wp1);
    cudaGetSymbolAddress((void**)&wp2_p,  g_wp2);

    // split-convert inputs once
    convert_split<<<(B_ * CIN_ * N_) / 1024, 256>>>(x, xh_p, xl_p, (B_ * CIN_ * N_) / 4);
    convert_w<<<dim3(OQKV_ / 64, CIN_ / 32), 256>>>(w_qkv, wp1_p, OQKV_, CIN_);
    convert_w<<<dim3(CIN_ / 64, HID_ / 32), 256>>>(w_out, wp2_p, CIN_, HID_);

    // 1) QKV projection: q/k m-tiles (0..3) single-pass bf16, v tiles (4,5) 3-pass
    gemm_mma<<<dim3(N_ / 64, OQKV_ / 64, B_), 256>>>(xh_p, xl_p, wp1_p, nullptr,
                                                     qkv_p, OQKV_, CIN_, 4);
    // 2) norms + folded scale, 3) bf16 tile pack, 4) attention (writes oh/ol)
    norm_kernel<<<B_ * HID_, 256>>>();
    pack_kernel<<<dim3(64, 16), 256>>>();
    attn_mma_kernel<<<dim3(N_ / 256, B_ * HEADS_), 256>>>();

    // 5) output projection on tensor cores (all tiles 3-pass)
    gemm_mma<<<dim3(N_ / 64, CIN_ / 64, B_), 256>>>(oh_p, ol_p, wp2_p, b_out,
                                                    y, CIN_, HID_, 0);
}

// round 13
// speedup vs baseline: 1.1412x; 1.1412x over previous
#include <cuda_runtime.h>
#include <cuda_bf16.h>
#include <math.h>
#include <cstdint>

#define B_     4
#define CIN_   256
#define N_     4096
#define HEADS_ 4
#define DH_    32
#define HID_   128
#define OQKV_  384
#define TPITCH 80u
#define TILEB  10240

// Scratch (allocation-free rule: __device__ globals)
__device__ float g_qkv[B_ * OQKV_ * N_];    // [b][o][n]: q 0..127, k 128..255, v 256..383
__device__ float g_scale[B_ * HID_];        // 10 / (||q_d|| ||k_d||)
__device__ float g_vsum[B_ * HID_];         // sum_j v[d][j]
__device__ __align__(16) unsigned char g_pack[16 * 64 * TILEB];  // attn K'/V bf16 tiles
// split-precision operands for the projection GEMMs
__device__ __align__(16) __nv_bfloat16 g_xh[B_ * CIN_ * N_];
__device__ __align__(16) __nv_bfloat16 g_xl[B_ * CIN_ * N_];
__device__ __align__(16) __nv_bfloat16 g_oh[B_ * HID_ * N_];   // attn out hi (written by attn)
__device__ __align__(16) __nv_bfloat16 g_ol[B_ * HID_ * N_];   // attn out lo
// W hi/lo packed into cp.async-ready 64m x 32k tiles (80B pitch rows, hi|lo)
__device__ __align__(16) unsigned char g_wp1[6 * 8 * TILEB];   // w_qkv: 384x256
__device__ __align__(16) unsigned char g_wp2[4 * 4 * TILEB];   // w_out: 256x128

// ---------------------------------------------------------------------------
// helpers
// ---------------------------------------------------------------------------
__device__ __forceinline__ uint32_t smem_to_u32(const void* p) {
    uint32_t a;
    asm("{ .reg .u64 t; cvta.to.shared.u64 t, %1; cvt.u32.u64 %0, t; }" : "=r"(a) : "l"(p));
    return a;
}

__device__ __forceinline__ void mma_bf16(float c[4],
                                         uint32_t a0, uint32_t a1, uint32_t a2, uint32_t a3,
                                         uint32_t b0, uint32_t b1) {
    asm volatile(
        "mma.sync.aligned.m16n8k16.row.col.f32.bf16.bf16.f32 "
        "{%0,%1,%2,%3}, {%4,%5,%6,%7}, {%8,%9}, {%0,%1,%2,%3};"
        : "+f"(c[0]), "+f"(c[1]), "+f"(c[2]), "+f"(c[3])
        : "r"(a0), "r"(a1), "r"(a2), "r"(a3), "r"(b0), "r"(b1));
}

// D = A.B + 0 : separate D/C, C = hoisted zero regs
__device__ __forceinline__ void mma_bf16_zc(float c[4],
                                            uint32_t a0, uint32_t a1, uint32_t a2, uint32_t a3,
                                            uint32_t b0, uint32_t b1) {
    asm volatile(
        "mma.sync.aligned.m16n8k16.row.col.f32.bf16.bf16.f32 "
        "{%0,%1,%2,%3}, {%4,%5,%6,%7}, {%8,%9}, {%10,%11,%12,%13};"
        : "=f"(c[0]), "=f"(c[1]), "=f"(c[2]), "=f"(c[3])
        : "r"(a0), "r"(a1), "r"(a2), "r"(a3), "r"(b0), "r"(b1),
          "f"(0.0f), "f"(0.0f), "f"(0.0f), "f"(0.0f));
}

__device__ __forceinline__ void ldsm4(uint32_t& r0, uint32_t& r1, uint32_t& r2, uint32_t& r3,
                                      uint32_t addr) {
    asm volatile("ldmatrix.sync.aligned.m8n8.x4.shared.b16 {%0,%1,%2,%3}, [%4];"
                 : "=r"(r0), "=r"(r1), "=r"(r2), "=r"(r3) : "r"(addr));
}
__device__ __forceinline__ void ldsm4t(uint32_t& r0, uint32_t& r1, uint32_t& r2, uint32_t& r3,
                                       uint32_t addr) {
    asm volatile("ldmatrix.sync.aligned.m8n8.x4.trans.shared.b16 {%0,%1,%2,%3}, [%4];"
                 : "=r"(r0), "=r"(r1), "=r"(r2), "=r"(r3) : "r"(addr));
}

__device__ __forceinline__ uint32_t packbf2(float lo, float hi) {
    __nv_bfloat162 p = __floats2bfloat162_rn(lo, hi);
    return *reinterpret_cast<uint32_t*>(&p);
}
__device__ __forceinline__ uint32_t bf2u(__nv_bfloat162 p) {
    return *reinterpret_cast<uint32_t*>(&p);
}

__device__ __forceinline__ void cp_async16(uint32_t s, const void* g) {
    asm volatile("cp.async.cg.shared.global [%0], [%1], 16;" :: "r"(s), "l"(g));
}

// ---------------------------------------------------------------------------
// convert_split: fp32 -> (bf16 hi, bf16 lo = x - hi), 4 elems/thread
// ---------------------------------------------------------------------------
__global__ void __launch_bounds__(256) convert_split(
    const float* __restrict__ src, __nv_bfloat16* __restrict__ hi,
    __nv_bfloat16* __restrict__ lo, int n4)
{
    int idx = blockIdx.x * 256 + threadIdx.x;
    if (idx >= n4) return;
    float4 f = reinterpret_cast<const float4*>(src)[idx];
    __nv_bfloat16 h0 = __float2bfloat16_rn(f.x);
    __nv_bfloat16 h1 = __float2bfloat16_rn(f.y);
    __nv_bfloat16 h2 = __float2bfloat16_rn(f.z);
    __nv_bfloat16 h3 = __float2bfloat16_rn(f.w);
    uint2 hw, lw;
    __nv_bfloat162 p01; p01.x = h0; p01.y = h1;
    __nv_bfloat162 p23; p23.x = h2; p23.y = h3;
    hw.x = bf2u(p01); hw.y = bf2u(p23);
    lw.x = packbf2(f.x - __bfloat162float(h0), f.y - __bfloat162float(h1));
    lw.y = packbf2(f.z - __bfloat162float(h2), f.w - __bfloat162float(h3));
    reinterpret_cast<uint2*>(hi)[idx] = hw;
    reinterpret_cast<uint2*>(lo)[idx] = lw;
}

// ---------------------------------------------------------------------------
// convert_w: W fp32 [M][K] -> packed tiles [mt][s][ hi 64x80B | lo 64x80B ]
// ---------------------------------------------------------------------------
__global__ void __launch_bounds__(256) convert_w(
    const float* __restrict__ W, unsigned char* __restrict__ dst, int M, int K)
{
    const int mt = blockIdx.x, s = blockIdx.y;
    const int m  = threadIdx.x & 63;
    const int kg = (threadIdx.x >> 6) * 8;
    unsigned char* base = dst + ((size_t)mt * (K >> 5) + s) * TILEB;
    const float* wrow = W + (size_t)(mt * 64 + m) * K + s * 32 + kg;

    #pragma unroll
    for (int p = 0; p < 4; p++) {
        float w0 = wrow[2 * p], w1 = wrow[2 * p + 1];
        __nv_bfloat16 h0 = __float2bfloat16_rn(w0);
        __nv_bfloat16 h1 = __float2bfloat16_rn(w1);
        __nv_bfloat162 ph; ph.x = h0; ph.y = h1;
        int k = kg + 2 * p;
        uint32_t off = (uint32_t)m * TPITCH + (uint32_t)((k >> 3) * 16 + (k & 7) * 2);
        *reinterpret_cast<uint32_t*>(base + off) = bf2u(ph);
        *reinterpret_cast<uint32_t*>(base + 5120 + off) =
            packbf2(w0 - __bfloat162float(h0), w1 - __bfloat162float(h1));
    }
}

// ---------------------------------------------------------------------------
// Split-bf16 tensor-core GEMM: out[b][m][n] = sum_k W[m][k] X[b][k][n] (+bias)
// m-tiles >= mt3: 3-pass (Xh.Wh + Xl.Wh + Xh.Wl). m-tiles < mt3: single-pass
// Xh.Wh — valid for q/k rows (self-consistent l2 normalization).
// ---------------------------------------------------------------------------
__global__ void __launch_bounds__(256) gemm_mma(
    const __nv_bfloat16* __restrict__ Xh, const __nv_bfloat16* __restrict__ Xl,
    const unsigned char* __restrict__ Wp, const float* __restrict__ bias,
    float* __restrict__ out, int M, int K, int mt3)
{
    __shared__ __align__(16) unsigned char smem[2][18432];

    const int tid = threadIdx.x, lane = tid & 31, w = tid >> 5;
    const int wn = w & 3, wm = w >> 2;
    const int g = lane >> 2, tg = lane & 3;
    const int n0 = blockIdx.x * 64, mt = blockIdx.y, b = blockIdx.z;
    const int nstages = K >> 5;
    const bool full = (mt >= mt3);

    const __nv_bfloat16* xh = Xh + (size_t)b * K * N_ + n0;
    const __nv_bfloat16* xl = Xl + (size_t)b * K * N_ + n0;
    const unsigned char* wp = Wp + (size_t)mt * nstages * TILEB;

    const int ck = tid >> 3, cc = tid & 7;
    const uint32_t xdst = (uint32_t)(ck * 128 + ((cc ^ (ck & 7)) * 16));

    auto issue = [&](int s) {
        uint32_t dst = smem_to_u32(smem[s & 1]);
        const char* sh = (const char*)(xh + (size_t)(s * 32 + ck) * N_) + cc * 16;
        cp_async16(dst + xdst, sh);
        if (full) {
            const char* sl = (const char*)(xl + (size_t)(s * 32 + ck) * N_) + cc * 16;
            cp_async16(dst + 4096 + xdst, sl);
        }
        const unsigned char* ws = wp + (size_t)s * TILEB;
        cp_async16(dst + 8192 + tid * 16, ws + tid * 16);
        cp_async16(dst + 8192 + (tid + 256) * 16, ws + (tid + 256) * 16);
        if (full && tid < 128)
            cp_async16(dst + 8192 + (tid + 512) * 16, ws + (tid + 512) * 16);
        asm volatile("cp.async.commit_group;" ::: "memory");
    };

    float acc[4][4] = {};

    issue(0);
    for (int s = 0; s < nstages; s++) {
        if (s + 1 < nstages) {
            issue(s + 1);
            asm volatile("cp.async.wait_group 1;" ::: "memory");
        } else {
            asm volatile("cp.async.wait_group 0;" ::: "memory");
        }
        __syncthreads();

        const uint32_t smX = smem_to_u32(smem[s & 1]);
        const uint32_t smW = smX + 8192;

        uint32_t Ah[2][4], Al[2][4];
        const int arow = ((lane & 16) >> 1) + (lane & 7);
        const int alog = wn * 2 + ((lane >> 3) & 1);
        #pragma unroll
        for (int ks = 0; ks < 2; ks++) {
            int kr = ks * 16 + arow;
            uint32_t aoff = (uint32_t)(kr * 128 + ((alog ^ (kr & 7)) * 16));
            ldsm4t(Ah[ks][0], Ah[ks][1], Ah[ks][2], Ah[ks][3], smX + aoff);
            if (full)
                ldsm4t(Al[ks][0], Al[ks][1], Al[ks][2], Al[ks][3], smX + 4096 + aoff);
        }

        #pragma unroll
        for (int mb = 0; mb < 4; mb++) {
            uint32_t waddr = smW + (uint32_t)((wm * 32 + mb * 8 + (lane & 7)) * TPITCH
                                              + (lane >> 3) * 16);
            uint32_t bh0, bh1, bh2, bh3;
            ldsm4(bh0, bh1, bh2, bh3, waddr);
            mma_bf16(acc[mb], Ah[0][0], Ah[0][1], Ah[0][2], Ah[0][3], bh0, bh1);
            mma_bf16(acc[mb], Ah[1][0], Ah[1][1], Ah[1][2], Ah[1][3], bh2, bh3);
            if (full) {
                uint32_t bl0, bl1, bl2, bl3;
                ldsm4(bl0, bl1, bl2, bl3, waddr + 5120);
                mma_bf16(acc[mb], Al[0][0], Al[0][1], Al[0][2], Al[0][3], bh0, bh1);
                mma_bf16(acc[mb], Al[1][0], Al[1][1], Al[1][2], Al[1][3], bh2, bh3);
                mma_bf16(acc[mb], Ah[0][0], Ah[0][1], Ah[0][2], Ah[0][3], bl0, bl1);
                mma_bf16(acc[mb], Ah[1][0], Ah[1][1], Ah[1][2], Ah[1][3], bl2, bl3);
            }
        }
        __syncthreads();
    }

    const int nA = n0 + wn * 16 + g, nB = nA + 8;
    #pragma unroll
    for (int mb = 0; mb < 4; mb++) {
        int m = mt * 64 + wm * 32 + mb * 8 + 2 * tg;
        float bv0 = bias ? bias[m] : 0.0f;
        float bv1 = bias ? bias[m + 1] : 0.0f;
        float* o0 = out + ((size_t)b * M + m) * N_;
        float* o1 = o0 + N_;
        o0[nA] = acc[mb][0] + bv0;
        o1[nA] = acc[mb][1] + bv1;
        o0[nB] = acc[mb][2] + bv0;
        o1[nB] = acc[mb][3] + bv1;
    }
}

// ---------------------------------------------------------------------------
// Per (b,hd): q,k row norms (-> folded scale) and v row sum.
// ---------------------------------------------------------------------------
__global__ void __launch_bounds__(256) norm_kernel()
{
    const int idx = blockIdx.x;
    const int b  = idx >> 7;
    const int hd = idx & 127;
    const float* q = g_qkv + ((size_t)(b * OQKV_ + hd)) * N_;
    const float* k = q + (size_t)HID_ * N_;
    const float* v = q + (size_t)(2 * HID_) * N_;

    float sq = 0.f, sk = 0.f, sv = 0.f;
    for (int i = threadIdx.x; i < N_; i += 256) {
        float a = q[i]; sq += a * a;
        float c = k[i]; sk += c * c;
        sv += v[i];
    }
    __shared__ float rq[256], rk[256], rv[256];
    rq[threadIdx.x] = sq; rk[threadIdx.x] = sk; rv[threadIdx.x] = sv;
    __syncthreads();
    for (int s = 128; s > 0; s >>= 1) {
        if (threadIdx.x < s) {
            rq[threadIdx.x] += rq[threadIdx.x + s];
            rk[threadIdx.x] += rk[threadIdx.x + s];
            rv[threadIdx.x] += rv[threadIdx.x + s];
        }
        __syncthreads();
    }
    if (threadIdx.x == 0) {
        float nq = fmaxf(sqrtf(rq[0]), 1e-12f);
        float nk = fmaxf(sqrtf(rk[0]), 1e-12f);
        g_scale[idx] = 10.0f / (nq * nk);
        g_vsum[idx]  = rv[0];
    }
}

// ---------------------------------------------------------------------------
// Pack K' (k * folded scale) and V into bf16 LDSM-ready tiles.
// ---------------------------------------------------------------------------
__global__ void __launch_bounds__(256) pack_kernel()
{
    const int bh = blockIdx.y, ti = blockIdx.x;
    const int b = bh >> 2, h = bh & 3;
    const float* kb = g_qkv + ((size_t)(b * OQKV_) + HID_ + h * DH_) * N_;
    const float* vb = kb + (size_t)HID_ * N_;

    const int j  = threadIdx.x & 63;
    const int dg = threadIdx.x >> 6;
    const int jt = ti * 64;
    unsigned char* out = g_pack + ((size_t)bh * 64 + ti) * TILEB;

    uint32_t kw[4], vw[4];
    #pragma unroll
    for (int p = 0; p < 4; p++) {
        int d = dg * 8 + 2 * p;
        float c0 = g_scale[bh * DH_ + d];
        float c1 = g_scale[bh * DH_ + d + 1];
        float k0 = kb[(size_t)d * N_ + jt + j];
        float k1 = kb[(size_t)(d + 1) * N_ + jt + j];
        kw[p] = packbf2(k0 * c0, k1 * c1);
        vw[p] = packbf2(vb[(size_t)d * N_ + jt + j], vb[(size_t)(d + 1) * N_ + jt + j]);
    }
    *(uint4*)(out + j * TPITCH + dg * 16)        = make_uint4(kw[0], kw[1], kw[2], kw[3]);
    *(uint4*)(out + 5120 + j * TPITCH + dg * 16) = make_uint4(vw[0], vw[1], vw[2], vw[3]);

    if (threadIdx.x < 64) {
        *(uint4*)(out + threadIdx.x * TPITCH + 64) = make_uint4(0u, 0u, 0u, 0u);
    } else if (threadIdx.x < 128) {
        int jj = threadIdx.x - 64;  // V pad: d=32 column of ones (lsum via MMA)
        *(uint4*)(out + 5120 + jj * TPITCH + 64) = make_uint4(0x00003F80u, 0u, 0u, 0u);
    }
}

// ---------------------------------------------------------------------------
// bf16 mma.sync flash attention — 128-thread CTAs (4 warps x 32 rows),
// 4 CTAs/SM: same 16 warps/SM and per-warp tile shape as the proven R9
// config, but barrier domains shrink 8 warps -> 4 and quadruple in count,
// so one CTA's __syncthreads no longer stalls half the SM's warps.
// No register cap (64K/512thr = 128/thr) — avoids the R12 spill failure.
// ---------------------------------------------------------------------------
__global__ void __launch_bounds__(128, 4) attn_mma_kernel()
{
    __shared__ __align__(16) unsigned char sbuf[4][TILEB];  // 40 KB

    const int tid  = threadIdx.x;
    const int lane = tid & 31;
    const int w    = tid >> 5;           // 0..3
    const int g    = lane >> 2;
    const int tg   = lane & 3;

    const int bh = blockIdx.y;
    const int b = bh >> 2, h = bh & 3;
    const int i0 = blockIdx.x * 128 + w * 32;   // warp owns 32 query rows

    const float* qb = g_qkv + ((size_t)(b * OQKV_) + h * DH_) * N_;
    const unsigned char* pk = g_pack + (size_t)bh * 64 * TILEB;

    // Q fragments: 2 m-blocks x 2 k-steps x 4
    uint32_t qa[2][2][4];
    #pragma unroll
    for (int m = 0; m < 2; m++) {
        #pragma unroll
        for (int ks = 0; ks < 2; ks++) {
            #pragma unroll
            for (int rr = 0; rr < 4; rr++) {
                int r = i0 + m * 16 + g + ((rr & 1) ? 8 : 0);
                int d = ks * 16 + 2 * tg + ((rr >> 1) ? 8 : 0);
                qa[m][ks][rr] = packbf2(qb[(size_t)d * N_ + r], qb[(size_t)(d + 1) * N_ + r]);
            }
        }
    }

    const __nv_bfloat162 C5  = __float2bfloat162_rn(0.5f);
    const __nv_bfloat162 ONE = __float2bfloat162_rn(1.0f);

    auto issue = [&](int ti) {
        const unsigned char* src = pk + (size_t)ti * TILEB;
        uint32_t dst = smem_to_u32(sbuf[ti & 3]);
        #pragma unroll
        for (int c = 0; c < 5; c++)   // 640 chunks / 128 threads = 5 each
            cp_async16(dst + (tid + c * 128) * 16, src + (tid + c * 128) * 16);
        asm volatile("cp.async.commit_group;" ::: "memory");
    };

    float oacc[2][5][4] = {};

    issue(0); issue(1); issue(2);

    for (int ti = 0; ti < 64; ti++) {
        asm volatile("cp.async.wait_group 2;" ::: "memory");
        __syncthreads();
        if (ti + 3 < 64) issue(ti + 3);   // buf consumed at ti-1, safe post-sync

        const uint32_t smK = smem_to_u32(sbuf[ti & 3]);
        const uint32_t smV = smK + 5120;

        #pragma unroll
        for (int hf = 0; hf < 2; hf++) {
            // S + epilogue per n-block: one K ldsm serves BOTH m-blocks
            uint32_t pa[2][2][4];   // [m][pair][frag]
            #pragma unroll
            for (int q4 = 0; q4 < 4; q4++) {
                uint32_t r0, r1, r2, r3;
                uint32_t jrow = (uint32_t)((hf * 4 + q4) * 8 + (lane & 7));
                ldsm4(r0, r1, r2, r3, smK + jrow * TPITCH + (uint32_t)(lane >> 3) * 16u);
                #pragma unroll
                for (int m = 0; m < 2; m++) {
                    float sc[4];
                    mma_bf16_zc(sc, qa[m][0][0], qa[m][0][1], qa[m][0][2], qa[m][0][3], r0, r1);
                    mma_bf16  (sc, qa[m][1][0], qa[m][1][1], qa[m][1][2], qa[m][1][3], r2, r3);
                    // delta = s * (1 + s/2)
                    __nv_bfloat162 s01 = __floats2bfloat162_rn(sc[0], sc[1]);
                    __nv_bfloat162 s23 = __floats2bfloat162_rn(sc[2], sc[3]);
                    __nv_bfloat162 t01 = __hfma2(s01, C5, ONE);
                    __nv_bfloat162 t23 = __hfma2(s23, C5, ONE);
                    pa[m][q4 >> 1][(q4 & 1) * 2 + 0] = bf2u(__hmul2(s01, t01));
                    pa[m][q4 >> 1][(q4 & 1) * 2 + 1] = bf2u(__hmul2(s23, t23));
                }
            }

            // PV: one V ldsm serves 2 m-blocks x 2 k-steps = 4 MMAs
            #pragma unroll
            for (int nbd = 0; nbd < 5; nbd++) {
                uint32_t v0, v1, v2, v3;
                ldsm4t(v0, v1, v2, v3,
                       smV + (uint32_t)(hf * 32 + lane) * TPITCH + (uint32_t)nbd * 16u);
                #pragma unroll
                for (int m = 0; m < 2; m++) {
                    mma_bf16(oacc[m][nbd], pa[m][0][0], pa[m][0][1], pa[m][0][2], pa[m][0][3], v0, v1);
                    mma_bf16(oacc[m][nbd], pa[m][1][0], pa[m][1][1], pa[m][1][2], pa[m][1][3], v2, v3);
                }
            }
        }
    }

    // per m-block: lsum in OUT col 32 (block 4, col 0) owned by tg=0 lanes
    const int chan0 = b * HID_ + h * DH_;
    #pragma unroll
    for (int m = 0; m < 2; m++) {
        float lA = __shfl_sync(0xffffffffu, oacc[m][4][0], lane & ~3);
        float lB = __shfl_sync(0xffffffffu, oacc[m][4][2], lane & ~3);
        const float rA = 1.0f / (4096.0f + lA);
        const float rB = 1.0f / (4096.0f + lB);
        const int iA = i0 + m * 16 + g, iB = iA + 8;
        #pragma unroll
        for (int nbd = 0; nbd < 4; nbd++) {
            int d0 = nbd * 8 + 2 * tg;
            float vs0 = g_vsum[chan0 + d0];
            float vs1 = g_vsum[chan0 + d0 + 1];
            float o00 = (vs0 + oacc[m][nbd][0]) * rA;
            float o10 = (vs1 + oacc[m][nbd][1]) * rA;
            float o01 = (vs0 + oacc[m][nbd][2]) * rB;
            float o11 = (vs1 + oacc[m][nbd][3]) * rB;
            size_t p0 = (size_t)(chan0 + d0) * N_;
            size_t p1 = p0 + N_;
            __nv_bfloat16 hh;
            hh = __float2bfloat16_rn(o00); g_oh[p0 + iA] = hh;
            g_ol[p0 + iA] = __float2bfloat16_rn(o00 - __bfloat162float(hh));
            hh = __float2bfloat16_rn(o10); g_oh[p1 + iA] = hh;
            g_ol[p1 + iA] = __float2bfloat16_rn(o10 - __bfloat162float(hh));
            hh = __float2bfloat16_rn(o01); g_oh[p0 + iB] = hh;
            g_ol[p0 + iB] = __float2bfloat16_rn(o01 - __bfloat162float(hh));
            hh = __float2bfloat16_rn(o11); g_oh[p1 + iB] = hh;
            g_ol[p1 + iB] = __float2bfloat16_rn(o11 - __bfloat162float(hh));
        }
    }
}

// ---------------------------------------------------------------------------
extern "C" void kernel_launch(void* const* d_in, const int* in_sizes, int n_in,
                              void* d_out, int out_size)
{
    (void)in_sizes; (void)n_in; (void)out_size;
    const float* x     = (const float*)d_in[0];
    const float* w_qkv = (const float*)d_in[1];
    const float* w_out = (const float*)d_in[2];
    const float* b_out = (const float*)d_in[3];
    float* y = (float*)d_out;

    float *qkv_p;
    __nv_bfloat16 *xh_p, *xl_p, *oh_p, *ol_p;
    unsigned char *wp1_p, *wp2_p;
    cudaGetSymbolAddress((void**)&qkv_p,  g_qkv);
    cudaGetSymbolAddress((void**)&xh_p,   g_xh);
    cudaGetSymbolAddress((void**)&xl_p,   g_xl);
    cudaGetSymbolAddress((void**)&oh_p,   g_oh);
    cudaGetSymbolAddress((void**)&ol_p,   g_ol);
    cudaGetSymbolAddress((void**)&wp1_p,  g_wp1);
    cudaGetSymbolAddress((void**)&wp2_p,  g_wp2);

    // split-convert inputs once
    convert_split<<<(B_ * CIN_ * N_) / 1024, 256>>>(x, xh_p, xl_p, (B_ * CIN_ * N_) / 4);
    convert_w<<<dim3(OQKV_ / 64, CIN_ / 32), 256>>>(w_qkv, wp1_p, OQKV_, CIN_);
    convert_w<<<dim3(CIN_ / 64, HID_ / 32), 256>>>(w_out, wp2_p, CIN_, HID_);

    // 1) QKV projection: q/k m-tiles (0..3) single-pass bf16, v tiles (4,5) 3-pass
    gemm_mma<<<dim3(N_ / 64, OQKV_ / 64, B_), 256>>>(xh_p, xl_p, wp1_p, nullptr,
                                                     qkv_p, OQKV_, CIN_, 4);
    // 2) norms + folded scale, 3) bf16 tile pack, 4) attention (writes oh/ol)
    norm_kernel<<<B_ * HID_, 256>>>();
    pack_kernel<<<dim3(64, 16), 256>>>();
    attn_mma_kernel<<<dim3(N_ / 128, B_ * HEADS_), 128>>>();

    // 5) output projection on tensor cores (all tiles 3-pass)
    gemm_mma<<<dim3(N_ / 64, CIN_ / 64, B_), 256>>>(oh_p, ol_p, wp2_p, b_out,
                                                    y, CIN_, HID_, 0);
}

// round 14
// speedup vs baseline: 1.1521x; 1.0095x over previous
#include <cuda_runtime.h>
#include <cuda_bf16.h>
#include <math.h>
#include <cstdint>

#define B_     4
#define CIN_   256
#define N_     4096
#define HEADS_ 4
#define DH_    32
#define HID_   128
#define OQKV_  384
#define TPITCH 80u
#define TILEB  10240

// Scratch (allocation-free rule: __device__ globals)
__device__ float g_qkv[B_ * OQKV_ * N_];    // [b][o][n]: q 0..127, k 128..255, v 256..383
__device__ float g_scale[B_ * HID_];        // 10 / (||q_d|| ||k_d||)
__device__ float g_vsum[B_ * HID_];         // sum_j v[d][j]
__device__ __align__(16) unsigned char g_pack[16 * 64 * TILEB];  // attn K'/V bf16 tiles
// split-precision operands for the projection GEMMs
__device__ __align__(16) __nv_bfloat16 g_xh[B_ * CIN_ * N_];
__device__ __align__(16) __nv_bfloat16 g_xl[B_ * CIN_ * N_];
__device__ __align__(16) __nv_bfloat16 g_oh[B_ * HID_ * N_];   // attn out hi (written by attn)
__device__ __align__(16) __nv_bfloat16 g_ol[B_ * HID_ * N_];   // attn out lo
// W hi/lo packed into cp.async-ready 64m x 32k tiles (80B pitch rows, hi|lo)
__device__ __align__(16) unsigned char g_wp1[6 * 8 * TILEB];   // w_qkv: 384x256
__device__ __align__(16) unsigned char g_wp2[4 * 4 * TILEB];   // w_out: 256x128

// ---------------------------------------------------------------------------
// helpers
// ---------------------------------------------------------------------------
__device__ __forceinline__ uint32_t smem_to_u32(const void* p) {
    uint32_t a;
    asm("{ .reg .u64 t; cvta.to.shared.u64 t, %1; cvt.u32.u64 %0, t; }" : "=r"(a) : "l"(p));
    return a;
}

__device__ __forceinline__ void mma_bf16(float c[4],
                                         uint32_t a0, uint32_t a1, uint32_t a2, uint32_t a3,
                                         uint32_t b0, uint32_t b1) {
    asm volatile(
        "mma.sync.aligned.m16n8k16.row.col.f32.bf16.bf16.f32 "
        "{%0,%1,%2,%3}, {%4,%5,%6,%7}, {%8,%9}, {%0,%1,%2,%3};"
        : "+f"(c[0]), "+f"(c[1]), "+f"(c[2]), "+f"(c[3])
        : "r"(a0), "r"(a1), "r"(a2), "r"(a3), "r"(b0), "r"(b1));
}

// D = A.B + 0 : separate D/C, C = hoisted zero regs
__device__ __forceinline__ void mma_bf16_zc(float c[4],
                                            uint32_t a0, uint32_t a1, uint32_t a2, uint32_t a3,
                                            uint32_t b0, uint32_t b1) {
    asm volatile(
        "mma.sync.aligned.m16n8k16.row.col.f32.bf16.bf16.f32 "
        "{%0,%1,%2,%3}, {%4,%5,%6,%7}, {%8,%9}, {%10,%11,%12,%13};"
        : "=f"(c[0]), "=f"(c[1]), "=f"(c[2]), "=f"(c[3])
        : "r"(a0), "r"(a1), "r"(a2), "r"(a3), "r"(b0), "r"(b1),
          "f"(0.0f), "f"(0.0f), "f"(0.0f), "f"(0.0f));
}

__device__ __forceinline__ void ldsm4(uint32_t& r0, uint32_t& r1, uint32_t& r2, uint32_t& r3,
                                      uint32_t addr) {
    asm volatile("ldmatrix.sync.aligned.m8n8.x4.shared.b16 {%0,%1,%2,%3}, [%4];"
                 : "=r"(r0), "=r"(r1), "=r"(r2), "=r"(r3) : "r"(addr));
}
__device__ __forceinline__ void ldsm4t(uint32_t& r0, uint32_t& r1, uint32_t& r2, uint32_t& r3,
                                       uint32_t addr) {
    asm volatile("ldmatrix.sync.aligned.m8n8.x4.trans.shared.b16 {%0,%1,%2,%3}, [%4];"
                 : "=r"(r0), "=r"(r1), "=r"(r2), "=r"(r3) : "r"(addr));
}

__device__ __forceinline__ uint32_t packbf2(float lo, float hi) {
    __nv_bfloat162 p = __floats2bfloat162_rn(lo, hi);
    return *reinterpret_cast<uint32_t*>(&p);
}
__device__ __forceinline__ uint32_t bf2u(__nv_bfloat162 p) {
    return *reinterpret_cast<uint32_t*>(&p);
}

__device__ __forceinline__ void cp_async16(uint32_t s, const void* g) {
    asm volatile("cp.async.cg.shared.global [%0], [%1], 16;" :: "r"(s), "l"(g));
}

// ---------------------------------------------------------------------------
// convert_split: fp32 -> (bf16 hi, bf16 lo = x - hi), 4 elems/thread
// ---------------------------------------------------------------------------
__global__ void __launch_bounds__(256) convert_split(
    const float* __restrict__ src, __nv_bfloat16* __restrict__ hi,
    __nv_bfloat16* __restrict__ lo, int n4)
{
    int idx = blockIdx.x * 256 + threadIdx.x;
    if (idx >= n4) return;
    float4 f = reinterpret_cast<const float4*>(src)[idx];
    __nv_bfloat16 h0 = __float2bfloat16_rn(f.x);
    __nv_bfloat16 h1 = __float2bfloat16_rn(f.y);
    __nv_bfloat16 h2 = __float2bfloat16_rn(f.z);
    __nv_bfloat16 h3 = __float2bfloat16_rn(f.w);
    uint2 hw, lw;
    __nv_bfloat162 p01; p01.x = h0; p01.y = h1;
    __nv_bfloat162 p23; p23.x = h2; p23.y = h3;
    hw.x = bf2u(p01); hw.y = bf2u(p23);
    lw.x = packbf2(f.x - __bfloat162float(h0), f.y - __bfloat162float(h1));
    lw.y = packbf2(f.z - __bfloat162float(h2), f.w - __bfloat162float(h3));
    reinterpret_cast<uint2*>(hi)[idx] = hw;
    reinterpret_cast<uint2*>(lo)[idx] = lw;
}

// ---------------------------------------------------------------------------
// convert_w: W fp32 [M][K] -> packed tiles [mt][s][ hi 64x80B | lo 64x80B ]
// ---------------------------------------------------------------------------
__global__ void __launch_bounds__(256) convert_w(
    const float* __restrict__ W, unsigned char* __restrict__ dst, int M, int K)
{
    const int mt = blockIdx.x, s = blockIdx.y;
    const int m  = threadIdx.x & 63;
    const int kg = (threadIdx.x >> 6) * 8;
    unsigned char* base = dst + ((size_t)mt * (K >> 5) + s) * TILEB;
    const float* wrow = W + (size_t)(mt * 64 + m) * K + s * 32 + kg;

    #pragma unroll
    for (int p = 0; p < 4; p++) {
        float w0 = wrow[2 * p], w1 = wrow[2 * p + 1];
        __nv_bfloat16 h0 = __float2bfloat16_rn(w0);
        __nv_bfloat16 h1 = __float2bfloat16_rn(w1);
        __nv_bfloat162 ph; ph.x = h0; ph.y = h1;
        int k = kg + 2 * p;
        uint32_t off = (uint32_t)m * TPITCH + (uint32_t)((k >> 3) * 16 + (k & 7) * 2);
        *reinterpret_cast<uint32_t*>(base + off) = bf2u(ph);
        *reinterpret_cast<uint32_t*>(base + 5120 + off) =
            packbf2(w0 - __bfloat162float(h0), w1 - __bfloat162float(h1));
    }
}

// ---------------------------------------------------------------------------
// Split-bf16 tensor-core GEMM: out[b][m][n] = sum_k W[m][k] X[b][k][n] (+bias)
// m-tiles >= mt3: 3-pass (Xh.Wh + Xl.Wh + Xh.Wl). m-tiles < mt3: single-pass
// Xh.Wh — valid for q/k rows (self-consistent l2 normalization).
// ---------------------------------------------------------------------------
__global__ void __launch_bounds__(256) gemm_mma(
    const __nv_bfloat16* __restrict__ Xh, const __nv_bfloat16* __restrict__ Xl,
    const unsigned char* __restrict__ Wp, const float* __restrict__ bias,
    float* __restrict__ out, int M, int K, int mt3)
{
    __shared__ __align__(16) unsigned char smem[2][18432];

    const int tid = threadIdx.x, lane = tid & 31, w = tid >> 5;
    const int wn = w & 3, wm = w >> 2;
    const int g = lane >> 2, tg = lane & 3;
    const int n0 = blockIdx.x * 64, mt = blockIdx.y, b = blockIdx.z;
    const int nstages = K >> 5;
    const bool full = (mt >= mt3);

    const __nv_bfloat16* xh = Xh + (size_t)b * K * N_ + n0;
    const __nv_bfloat16* xl = Xl + (size_t)b * K * N_ + n0;
    const unsigned char* wp = Wp + (size_t)mt * nstages * TILEB;

    const int ck = tid >> 3, cc = tid & 7;
    const uint32_t xdst = (uint32_t)(ck * 128 + ((cc ^ (ck & 7)) * 16));

    auto issue = [&](int s) {
        uint32_t dst = smem_to_u32(smem[s & 1]);
        const char* sh = (const char*)(xh + (size_t)(s * 32 + ck) * N_) + cc * 16;
        cp_async16(dst + xdst, sh);
        if (full) {
            const char* sl = (const char*)(xl + (size_t)(s * 32 + ck) * N_) + cc * 16;
            cp_async16(dst + 4096 + xdst, sl);
        }
        const unsigned char* ws = wp + (size_t)s * TILEB;
        cp_async16(dst + 8192 + tid * 16, ws + tid * 16);
        cp_async16(dst + 8192 + (tid + 256) * 16, ws + (tid + 256) * 16);
        if (full && tid < 128)
            cp_async16(dst + 8192 + (tid + 512) * 16, ws + (tid + 512) * 16);
        asm volatile("cp.async.commit_group;" ::: "memory");
    };

    float acc[4][4] = {};

    issue(0);
    for (int s = 0; s < nstages; s++) {
        if (s + 1 < nstages) {
            issue(s + 1);
            asm volatile("cp.async.wait_group 1;" ::: "memory");
        } else {
            asm volatile("cp.async.wait_group 0;" ::: "memory");
        }
        __syncthreads();

        const uint32_t smX = smem_to_u32(smem[s & 1]);
        const uint32_t smW = smX + 8192;

        uint32_t Ah[2][4], Al[2][4];
        const int arow = ((lane & 16) >> 1) + (lane & 7);
        const int alog = wn * 2 + ((lane >> 3) & 1);
        #pragma unroll
        for (int ks = 0; ks < 2; ks++) {
            int kr = ks * 16 + arow;
            uint32_t aoff = (uint32_t)(kr * 128 + ((alog ^ (kr & 7)) * 16));
            ldsm4t(Ah[ks][0], Ah[ks][1], Ah[ks][2], Ah[ks][3], smX + aoff);
            if (full)
                ldsm4t(Al[ks][0], Al[ks][1], Al[ks][2], Al[ks][3], smX + 4096 + aoff);
        }

        #pragma unroll
        for (int mb = 0; mb < 4; mb++) {
            uint32_t waddr = smW + (uint32_t)((wm * 32 + mb * 8 + (lane & 7)) * TPITCH
                                              + (lane >> 3) * 16);
            uint32_t bh0, bh1, bh2, bh3;
            ldsm4(bh0, bh1, bh2, bh3, waddr);
            mma_bf16(acc[mb], Ah[0][0], Ah[0][1], Ah[0][2], Ah[0][3], bh0, bh1);
            mma_bf16(acc[mb], Ah[1][0], Ah[1][1], Ah[1][2], Ah[1][3], bh2, bh3);
            if (full) {
                uint32_t bl0, bl1, bl2, bl3;
                ldsm4(bl0, bl1, bl2, bl3, waddr + 5120);
                mma_bf16(acc[mb], Al[0][0], Al[0][1], Al[0][2], Al[0][3], bh0, bh1);
                mma_bf16(acc[mb], Al[1][0], Al[1][1], Al[1][2], Al[1][3], bh2, bh3);
                mma_bf16(acc[mb], Ah[0][0], Ah[0][1], Ah[0][2], Ah[0][3], bl0, bl1);
                mma_bf16(acc[mb], Ah[1][0], Ah[1][1], Ah[1][2], Ah[1][3], bl2, bl3);
            }
        }
        __syncthreads();
    }

    const int nA = n0 + wn * 16 + g, nB = nA + 8;
    #pragma unroll
    for (int mb = 0; mb < 4; mb++) {
        int m = mt * 64 + wm * 32 + mb * 8 + 2 * tg;
        float bv0 = bias ? bias[m] : 0.0f;
        float bv1 = bias ? bias[m + 1] : 0.0f;
        float* o0 = out + ((size_t)b * M + m) * N_;
        float* o1 = o0 + N_;
        o0[nA] = acc[mb][0] + bv0;
        o1[nA] = acc[mb][1] + bv1;
        o0[nB] = acc[mb][2] + bv0;
        o1[nB] = acc[mb][3] + bv1;
    }
}

// ---------------------------------------------------------------------------
// Per (b,hd): q,k row norms (-> folded scale) and v row sum.
// ---------------------------------------------------------------------------
__global__ void __launch_bounds__(256) norm_kernel()
{
    const int idx = blockIdx.x;
    const int b  = idx >> 7;
    const int hd = idx & 127;
    const float* q = g_qkv + ((size_t)(b * OQKV_ + hd)) * N_;
    const float* k = q + (size_t)HID_ * N_;
    const float* v = q + (size_t)(2 * HID_) * N_;

    float sq = 0.f, sk = 0.f, sv = 0.f;
    for (int i = threadIdx.x; i < N_; i += 256) {
        float a = q[i]; sq += a * a;
        float c = k[i]; sk += c * c;
        sv += v[i];
    }
    __shared__ float rq[256], rk[256], rv[256];
    rq[threadIdx.x] = sq; rk[threadIdx.x] = sk; rv[threadIdx.x] = sv;
    __syncthreads();
    for (int s = 128; s > 0; s >>= 1) {
        if (threadIdx.x < s) {
            rq[threadIdx.x] += rq[threadIdx.x + s];
            rk[threadIdx.x] += rk[threadIdx.x + s];
            rv[threadIdx.x] += rv[threadIdx.x + s];
        }
        __syncthreads();
    }
    if (threadIdx.x == 0) {
        float nq = fmaxf(sqrtf(rq[0]), 1e-12f);
        float nk = fmaxf(sqrtf(rk[0]), 1e-12f);
        g_scale[idx] = 10.0f / (nq * nk);
        g_vsum[idx]  = rv[0];
    }
}

// ---------------------------------------------------------------------------
// Pack K' (k * folded scale) and V into bf16 LDSM-ready tiles.
// (pad chunks no longer read by attention -> no pad writes needed)
// ---------------------------------------------------------------------------
__global__ void __launch_bounds__(256) pack_kernel()
{
    const int bh = blockIdx.y, ti = blockIdx.x;
    const int b = bh >> 2, h = bh & 3;
    const float* kb = g_qkv + ((size_t)(b * OQKV_) + HID_ + h * DH_) * N_;
    const float* vb = kb + (size_t)HID_ * N_;

    const int j  = threadIdx.x & 63;
    const int dg = threadIdx.x >> 6;
    const int jt = ti * 64;
    unsigned char* out = g_pack + ((size_t)bh * 64 + ti) * TILEB;

    uint32_t kw[4], vw[4];
    #pragma unroll
    for (int p = 0; p < 4; p++) {
        int d = dg * 8 + 2 * p;
        float c0 = g_scale[bh * DH_ + d];
        float c1 = g_scale[bh * DH_ + d + 1];
        float k0 = kb[(size_t)d * N_ + jt + j];
        float k1 = kb[(size_t)(d + 1) * N_ + jt + j];
        kw[p] = packbf2(k0 * c0, k1 * c1);
        vw[p] = packbf2(vb[(size_t)d * N_ + jt + j], vb[(size_t)(d + 1) * N_ + jt + j]);
    }
    *(uint4*)(out + j * TPITCH + dg * 16)        = make_uint4(kw[0], kw[1], kw[2], kw[3]);
    *(uint4*)(out + 5120 + j * TPITCH + dg * 16) = make_uint4(vw[0], vw[1], vw[2], vw[3]);
}

// ---------------------------------------------------------------------------
// bf16 mma.sync flash attention — 128-thread CTAs, 4 CTAs/SM (R13 shape).
// lsum moved OFF the tensor pipe: accumulated in bf16x2 HADD2 on the delta
// registers (FMA pipe, idle) instead of the ones-column MMA. PV: 40->32 MMAs
// per warp-tile (-11% tensor work, the measured bottleneck), V ldsm 5->4.
// ---------------------------------------------------------------------------
__global__ void __launch_bounds__(128, 4) attn_mma_kernel()
{
    __shared__ __align__(16) unsigned char sbuf[4][TILEB];  // 40 KB

    const int tid  = threadIdx.x;
    const int lane = tid & 31;
    const int w    = tid >> 5;           // 0..3
    const int g    = lane >> 2;
    const int tg   = lane & 3;

    const int bh = blockIdx.y;
    const int b = bh >> 2, h = bh & 3;
    const int i0 = blockIdx.x * 128 + w * 32;   // warp owns 32 query rows

    const float* qb = g_qkv + ((size_t)(b * OQKV_) + h * DH_) * N_;
    const unsigned char* pk = g_pack + (size_t)bh * 64 * TILEB;

    // Q fragments: 2 m-blocks x 2 k-steps x 4
    uint32_t qa[2][2][4];
    #pragma unroll
    for (int m = 0; m < 2; m++) {
        #pragma unroll
        for (int ks = 0; ks < 2; ks++) {
            #pragma unroll
            for (int rr = 0; rr < 4; rr++) {
                int r = i0 + m * 16 + g + ((rr & 1) ? 8 : 0);
                int d = ks * 16 + 2 * tg + ((rr >> 1) ? 8 : 0);
                qa[m][ks][rr] = packbf2(qb[(size_t)d * N_ + r], qb[(size_t)(d + 1) * N_ + r]);
            }
        }
    }

    const __nv_bfloat162 C5   = __float2bfloat162_rn(0.5f);
    const __nv_bfloat162 ONE  = __float2bfloat162_rn(1.0f);
    const __nv_bfloat162 ZERO = __float2bfloat162_rn(0.0f);

    auto issue = [&](int ti) {
        const unsigned char* src = pk + (size_t)ti * TILEB;
        uint32_t dst = smem_to_u32(sbuf[ti & 3]);
        #pragma unroll
        for (int c = 0; c < 5; c++)   // 640 chunks / 128 threads = 5 each
            cp_async16(dst + (tid + c * 128) * 16, src + (tid + c * 128) * 16);
        asm volatile("cp.async.commit_group;" ::: "memory");
    };

    float oacc[2][4][4] = {};
    __nv_bfloat162 ls[2][2] = {{ZERO, ZERO}, {ZERO, ZERO}};  // [m][row half g / g+8]

    issue(0); issue(1); issue(2);

    for (int ti = 0; ti < 64; ti++) {
        asm volatile("cp.async.wait_group 2;" ::: "memory");
        __syncthreads();
        if (ti + 3 < 64) issue(ti + 3);   // buf consumed at ti-1, safe post-sync

        const uint32_t smK = smem_to_u32(sbuf[ti & 3]);
        const uint32_t smV = smK + 5120;

        #pragma unroll
        for (int hf = 0; hf < 2; hf++) {
            // S + epilogue per n-block: one K ldsm serves BOTH m-blocks
            uint32_t pa[2][2][4];   // [m][pair][frag]
            #pragma unroll
            for (int q4 = 0; q4 < 4; q4++) {
                uint32_t r0, r1, r2, r3;
                uint32_t jrow = (uint32_t)((hf * 4 + q4) * 8 + (lane & 7));
                ldsm4(r0, r1, r2, r3, smK + jrow * TPITCH + (uint32_t)(lane >> 3) * 16u);
                #pragma unroll
                for (int m = 0; m < 2; m++) {
                    float sc[4];
                    mma_bf16_zc(sc, qa[m][0][0], qa[m][0][1], qa[m][0][2], qa[m][0][3], r0, r1);
                    mma_bf16  (sc, qa[m][1][0], qa[m][1][1], qa[m][1][2], qa[m][1][3], r2, r3);
                    // delta = s * (1 + s/2); lsum accumulated on FMA pipe
                    __nv_bfloat162 s01 = __floats2bfloat162_rn(sc[0], sc[1]);
                    __nv_bfloat162 s23 = __floats2bfloat162_rn(sc[2], sc[3]);
                    __nv_bfloat162 t01 = __hfma2(s01, C5, ONE);
                    __nv_bfloat162 t23 = __hfma2(s23, C5, ONE);
                    __nv_bfloat162 d01 = __hmul2(s01, t01);
                    __nv_bfloat162 d23 = __hmul2(s23, t23);
                    ls[m][0] = __hadd2(ls[m][0], d01);
                    ls[m][1] = __hadd2(ls[m][1], d23);
                    pa[m][q4 >> 1][(q4 & 1) * 2 + 0] = bf2u(d01);
                    pa[m][q4 >> 1][(q4 & 1) * 2 + 1] = bf2u(d23);
                }
            }

            // PV: one V ldsm serves 2 m-blocks x 2 k-steps = 4 MMAs
            #pragma unroll
            for (int nbd = 0; nbd < 4; nbd++) {
                uint32_t v0, v1, v2, v3;
                ldsm4t(v0, v1, v2, v3,
                       smV + (uint32_t)(hf * 32 + lane) * TPITCH + (uint32_t)nbd * 16u);
                #pragma unroll
                for (int m = 0; m < 2; m++) {
                    mma_bf16(oacc[m][nbd], pa[m][0][0], pa[m][0][1], pa[m][0][2], pa[m][0][3], v0, v1);
                    mma_bf16(oacc[m][nbd], pa[m][1][0], pa[m][1][1], pa[m][1][2], pa[m][1][3], v2, v3);
                }
            }
        }
    }

    // per m-block: reduce lsum across the 4 tg lanes of each row group
    const int chan0 = b * HID_ + h * DH_;
    #pragma unroll
    for (int m = 0; m < 2; m++) {
        float lA = __bfloat162float(ls[m][0].x) + __bfloat162float(ls[m][0].y);
        float lB = __bfloat162float(ls[m][1].x) + __bfloat162float(ls[m][1].y);
        lA += __shfl_xor_sync(0xffffffffu, lA, 1);
        lA += __shfl_xor_sync(0xffffffffu, lA, 2);
        lB += __shfl_xor_sync(0xffffffffu, lB, 1);
        lB += __shfl_xor_sync(0xffffffffu, lB, 2);
        const float rA = 1.0f / (4096.0f + lA);
        const float rB = 1.0f / (4096.0f + lB);
        const int iA = i0 + m * 16 + g, iB = iA + 8;
        #pragma unroll
        for (int nbd = 0; nbd < 4; nbd++) {
            int d0 = nbd * 8 + 2 * tg;
            float vs0 = g_vsum[chan0 + d0];
            float vs1 = g_vsum[chan0 + d0 + 1];
            float o00 = (vs0 + oacc[m][nbd][0]) * rA;
            float o10 = (vs1 + oacc[m][nbd][1]) * rA;
            float o01 = (vs0 + oacc[m][nbd][2]) * rB;
            float o11 = (vs1 + oacc[m][nbd][3]) * rB;
            size_t p0 = (size_t)(chan0 + d0) * N_;
            size_t p1 = p0 + N_;
            __nv_bfloat16 hh;
            hh = __float2bfloat16_rn(o00); g_oh[p0 + iA] = hh;
            g_ol[p0 + iA] = __float2bfloat16_rn(o00 - __bfloat162float(hh));
            hh = __float2bfloat16_rn(o10); g_oh[p1 + iA] = hh;
            g_ol[p1 + iA] = __float2bfloat16_rn(o10 - __bfloat162float(hh));
            hh = __float2bfloat16_rn(o01); g_oh[p0 + iB] = hh;
            g_ol[p0 + iB] = __float2bfloat16_rn(o01 - __bfloat162float(hh));
            hh = __float2bfloat16_rn(o11); g_oh[p1 + iB] = hh;
            g_ol[p1 + iB] = __float2bfloat16_rn(o11 - __bfloat162float(hh));
        }
    }
}

// ---------------------------------------------------------------------------
extern "C" void kernel_launch(void* const* d_in, const int* in_sizes, int n_in,
                              void* d_out, int out_size)
{
    (void)in_sizes; (void)n_in; (void)out_size;
    const float* x     = (const float*)d_in[0];
    const float* w_qkv = (const float*)d_in[1];
    const float* w_out = (const float*)d_in[2];
    const float* b_out = (const float*)d_in[3];
    float* y = (float*)d_out;

    float *qkv_p;
    __nv_bfloat16 *xh_p, *xl_p, *oh_p, *ol_p;
    unsigned char *wp1_p, *wp2_p;
    cudaGetSymbolAddress((void**)&qkv_p,  g_qkv);
    cudaGetSymbolAddress((void**)&xh_p,   g_xh);
    cudaGetSymbolAddress((void**)&xl_p,   g_xl);
    cudaGetSymbolAddress((void**)&oh_p,   g_oh);
    cudaGetSymbolAddress((void**)&ol_p,   g_ol);
    cudaGetSymbolAddress((void**)&wp1_p,  g_wp1);
    cudaGetSymbolAddress((void**)&wp2_p,  g_wp2);

    // split-convert inputs once
    convert_split<<<(B_ * CIN_ * N_) / 1024, 256>>>(x, xh_p, xl_p, (B_ * CIN_ * N_) / 4);
    convert_w<<<dim3(OQKV_ / 64, CIN_ / 32), 256>>>(w_qkv, wp1_p, OQKV_, CIN_);
    convert_w<<<dim3(CIN_ / 64, HID_ / 32), 256>>>(w_out, wp2_p, CIN_, HID_);

    // 1) QKV projection: q/k m-tiles (0..3) single-pass bf16, v tiles (4,5) 3-pass
    gemm_mma<<<dim3(N_ / 64, OQKV_ / 64, B_), 256>>>(xh_p, xl_p, wp1_p, nullptr,
                                                     qkv_p, OQKV_, CIN_, 4);
    // 2) norms + folded scale, 3) bf16 tile pack, 4) attention (writes oh/ol)
    norm_kernel<<<B_ * HID_, 256>>>();
    pack_kernel<<<dim3(64, 16), 256>>>();
    attn_mma_kernel<<<dim3(N_ / 128, B_ * HEADS_), 128>>>();

    // 5) output projection on tensor cores (all tiles 3-pass)
    gemm_mma<<<dim3(N_ / 64, CIN_ / 64, B_), 256>>>(oh_p, ol_p, wp2_p, b_out,
                                                    y, CIN_, HID_, 0);
}

// round 15
// speedup vs baseline: 1.1658x; 1.0119x over previous
#include <cuda_runtime.h>
#include <cuda_bf16.h>
#include <math.h>
#include <cstdint>

#define B_     4
#define CIN_   256
#define N_     4096
#define HEADS_ 4
#define DH_    32
#define HID_   128
#define OQKV_  384
#define TPITCH 80u
#define TILEB  10240

// Scratch (allocation-free rule: __device__ globals)
__device__ float g_qkv[B_ * OQKV_ * N_];    // [b][o][n]: q 0..127, k 128..255, v 256..383
__device__ float g_scale[B_ * HID_];        // 10 / (||q_d|| ||k_d||)
__device__ float g_vsum[B_ * HID_];         // sum_j v[d][j]
__device__ __align__(16) unsigned char g_pack[16 * 64 * TILEB];  // attn K'/V bf16 tiles
// split-precision operands for the projection GEMMs
__device__ __align__(16) __nv_bfloat16 g_xh[B_ * CIN_ * N_];
__device__ __align__(16) __nv_bfloat16 g_xl[B_ * CIN_ * N_];
__device__ __align__(16) __nv_bfloat16 g_oh[B_ * HID_ * N_];   // attn out hi (written by attn)
__device__ __align__(16) __nv_bfloat16 g_ol[B_ * HID_ * N_];   // attn out lo
// W hi/lo packed into cp.async-ready 64m x 32k tiles (80B pitch rows, hi|lo)
__device__ __align__(16) unsigned char g_wp1[6 * 8 * TILEB];   // w_qkv: 384x256
__device__ __align__(16) unsigned char g_wp2[4 * 4 * TILEB];   // w_out: 256x128

// ---------------------------------------------------------------------------
// helpers
// ---------------------------------------------------------------------------
__device__ __forceinline__ uint32_t smem_to_u32(const void* p) {
    uint32_t a;
    asm("{ .reg .u64 t; cvta.to.shared.u64 t, %1; cvt.u32.u64 %0, t; }" : "=r"(a) : "l"(p));
    return a;
}

__device__ __forceinline__ void mma_bf16(float c[4],
                                         uint32_t a0, uint32_t a1, uint32_t a2, uint32_t a3,
                                         uint32_t b0, uint32_t b1) {
    asm volatile(
        "mma.sync.aligned.m16n8k16.row.col.f32.bf16.bf16.f32 "
        "{%0,%1,%2,%3}, {%4,%5,%6,%7}, {%8,%9}, {%0,%1,%2,%3};"
        : "+f"(c[0]), "+f"(c[1]), "+f"(c[2]), "+f"(c[3])
        : "r"(a0), "r"(a1), "r"(a2), "r"(a3), "r"(b0), "r"(b1));
}

// D = A.B + 0 : separate D/C, C = hoisted zero regs
__device__ __forceinline__ void mma_bf16_zc(float c[4],
                                            uint32_t a0, uint32_t a1, uint32_t a2, uint32_t a3,
                                            uint32_t b0, uint32_t b1) {
    asm volatile(
        "mma.sync.aligned.m16n8k16.row.col.f32.bf16.bf16.f32 "
        "{%0,%1,%2,%3}, {%4,%5,%6,%7}, {%8,%9}, {%10,%11,%12,%13};"
        : "=f"(c[0]), "=f"(c[1]), "=f"(c[2]), "=f"(c[3])
        : "r"(a0), "r"(a1), "r"(a2), "r"(a3), "r"(b0), "r"(b1),
          "f"(0.0f), "f"(0.0f), "f"(0.0f), "f"(0.0f));
}

__device__ __forceinline__ void ldsm4(uint32_t& r0, uint32_t& r1, uint32_t& r2, uint32_t& r3,
                                      uint32_t addr) {
    asm volatile("ldmatrix.sync.aligned.m8n8.x4.shared.b16 {%0,%1,%2,%3}, [%4];"
                 : "=r"(r0), "=r"(r1), "=r"(r2), "=r"(r3) : "r"(addr));
}
__device__ __forceinline__ void ldsm4t(uint32_t& r0, uint32_t& r1, uint32_t& r2, uint32_t& r3,
                                       uint32_t addr) {
    asm volatile("ldmatrix.sync.aligned.m8n8.x4.trans.shared.b16 {%0,%1,%2,%3}, [%4];"
                 : "=r"(r0), "=r"(r1), "=r"(r2), "=r"(r3) : "r"(addr));
}

__device__ __forceinline__ uint32_t packbf2(float lo, float hi) {
    __nv_bfloat162 p = __floats2bfloat162_rn(lo, hi);
    return *reinterpret_cast<uint32_t*>(&p);
}
__device__ __forceinline__ uint32_t bf2u(__nv_bfloat162 p) {
    return *reinterpret_cast<uint32_t*>(&p);
}

__device__ __forceinline__ void cp_async16(uint32_t s, const void* g) {
    asm volatile("cp.async.cg.shared.global [%0], [%1], 16;" :: "r"(s), "l"(g));
}

// ---------------------------------------------------------------------------
// convert_split: fp32 -> (bf16 hi, bf16 lo = x - hi), 4 elems/thread
// ---------------------------------------------------------------------------
__global__ void __launch_bounds__(256) convert_split(
    const float* __restrict__ src, __nv_bfloat16* __restrict__ hi,
    __nv_bfloat16* __restrict__ lo, int n4)
{
    int idx = blockIdx.x * 256 + threadIdx.x;
    if (idx >= n4) return;
    float4 f = reinterpret_cast<const float4*>(src)[idx];
    __nv_bfloat16 h0 = __float2bfloat16_rn(f.x);
    __nv_bfloat16 h1 = __float2bfloat16_rn(f.y);
    __nv_bfloat16 h2 = __float2bfloat16_rn(f.z);
    __nv_bfloat16 h3 = __float2bfloat16_rn(f.w);
    uint2 hw, lw;
    __nv_bfloat162 p01; p01.x = h0; p01.y = h1;
    __nv_bfloat162 p23; p23.x = h2; p23.y = h3;
    hw.x = bf2u(p01); hw.y = bf2u(p23);
    lw.x = packbf2(f.x - __bfloat162float(h0), f.y - __bfloat162float(h1));
    lw.y = packbf2(f.z - __bfloat162float(h2), f.w - __bfloat162float(h3));
    reinterpret_cast<uint2*>(hi)[idx] = hw;
    reinterpret_cast<uint2*>(lo)[idx] = lw;
}

// ---------------------------------------------------------------------------
// convert_w: W fp32 [M][K] -> packed tiles [mt][s][ hi 64x80B | lo 64x80B ]
// ---------------------------------------------------------------------------
__global__ void __launch_bounds__(256) convert_w(
    const float* __restrict__ W, unsigned char* __restrict__ dst, int M, int K)
{
    const int mt = blockIdx.x, s = blockIdx.y;
    const int m  = threadIdx.x & 63;
    const int kg = (threadIdx.x >> 6) * 8;
    unsigned char* base = dst + ((size_t)mt * (K >> 5) + s) * TILEB;
    const float* wrow = W + (size_t)(mt * 64 + m) * K + s * 32 + kg;

    #pragma unroll
    for (int p = 0; p < 4; p++) {
        float w0 = wrow[2 * p], w1 = wrow[2 * p + 1];
        __nv_bfloat16 h0 = __float2bfloat16_rn(w0);
        __nv_bfloat16 h1 = __float2bfloat16_rn(w1);
        __nv_bfloat162 ph; ph.x = h0; ph.y = h1;
        int k = kg + 2 * p;
        uint32_t off = (uint32_t)m * TPITCH + (uint32_t)((k >> 3) * 16 + (k & 7) * 2);
        *reinterpret_cast<uint32_t*>(base + off) = bf2u(ph);
        *reinterpret_cast<uint32_t*>(base + 5120 + off) =
            packbf2(w0 - __bfloat162float(h0), w1 - __bfloat162float(h1));
    }
}

// ---------------------------------------------------------------------------
// Split-bf16 tensor-core GEMM: out[b][m][n] = sum_k W[m][k] X[b][k][n] (+bias)
// m-tiles >= mt3: 3-pass (Xh.Wh + Xl.Wh + Xh.Wl). m-tiles < mt3: single-pass
// Xh.Wh — valid for q/k rows (self-consistent l2 normalization).
// ---------------------------------------------------------------------------
__global__ void __launch_bounds__(256) gemm_mma(
    const __nv_bfloat16* __restrict__ Xh, const __nv_bfloat16* __restrict__ Xl,
    const unsigned char* __restrict__ Wp, const float* __restrict__ bias,
    float* __restrict__ out, int M, int K, int mt3)
{
    __shared__ __align__(16) unsigned char smem[2][18432];

    const int tid = threadIdx.x, lane = tid & 31, w = tid >> 5;
    const int wn = w & 3, wm = w >> 2;
    const int g = lane >> 2, tg = lane & 3;
    const int n0 = blockIdx.x * 64, mt = blockIdx.y, b = blockIdx.z;
    const int nstages = K >> 5;
    const bool full = (mt >= mt3);

    const __nv_bfloat16* xh = Xh + (size_t)b * K * N_ + n0;
    const __nv_bfloat16* xl = Xl + (size_t)b * K * N_ + n0;
    const unsigned char* wp = Wp + (size_t)mt * nstages * TILEB;

    const int ck = tid >> 3, cc = tid & 7;
    const uint32_t xdst = (uint32_t)(ck * 128 + ((cc ^ (ck & 7)) * 16));

    auto issue = [&](int s) {
        uint32_t dst = smem_to_u32(smem[s & 1]);
        const char* sh = (const char*)(xh + (size_t)(s * 32 + ck) * N_) + cc * 16;
        cp_async16(dst + xdst, sh);
        if (full) {
            const char* sl = (const char*)(xl + (size_t)(s * 32 + ck) * N_) + cc * 16;
            cp_async16(dst + 4096 + xdst, sl);
        }
        const unsigned char* ws = wp + (size_t)s * TILEB;
        cp_async16(dst + 8192 + tid * 16, ws + tid * 16);
        cp_async16(dst + 8192 + (tid + 256) * 16, ws + (tid + 256) * 16);
        if (full && tid < 128)
            cp_async16(dst + 8192 + (tid + 512) * 16, ws + (tid + 512) * 16);
        asm volatile("cp.async.commit_group;" ::: "memory");
    };

    float acc[4][4] = {};

    issue(0);
    for (int s = 0; s < nstages; s++) {
        if (s + 1 < nstages) {
            issue(s + 1);
            asm volatile("cp.async.wait_group 1;" ::: "memory");
        } else {
            asm volatile("cp.async.wait_group 0;" ::: "memory");
        }
        __syncthreads();

        const uint32_t smX = smem_to_u32(smem[s & 1]);
        const uint32_t smW = smX + 8192;

        uint32_t Ah[2][4], Al[2][4];
        const int arow = ((lane & 16) >> 1) + (lane & 7);
        const int alog = wn * 2 + ((lane >> 3) & 1);
        #pragma unroll
        for (int ks = 0; ks < 2; ks++) {
            int kr = ks * 16 + arow;
            uint32_t aoff = (uint32_t)(kr * 128 + ((alog ^ (kr & 7)) * 16));
            ldsm4t(Ah[ks][0], Ah[ks][1], Ah[ks][2], Ah[ks][3], smX + aoff);
            if (full)
                ldsm4t(Al[ks][0], Al[ks][1], Al[ks][2], Al[ks][3], smX + 4096 + aoff);
        }

        #pragma unroll
        for (int mb = 0; mb < 4; mb++) {
            uint32_t waddr = smW + (uint32_t)((wm * 32 + mb * 8 + (lane & 7)) * TPITCH
                                              + (lane >> 3) * 16);
            uint32_t bh0, bh1, bh2, bh3;
            ldsm4(bh0, bh1, bh2, bh3, waddr);
            mma_bf16(acc[mb], Ah[0][0], Ah[0][1], Ah[0][2], Ah[0][3], bh0, bh1);
            mma_bf16(acc[mb], Ah[1][0], Ah[1][1], Ah[1][2], Ah[1][3], bh2, bh3);
            if (full) {
                uint32_t bl0, bl1, bl2, bl3;
                ldsm4(bl0, bl1, bl2, bl3, waddr + 5120);
                mma_bf16(acc[mb], Al[0][0], Al[0][1], Al[0][2], Al[0][3], bh0, bh1);
                mma_bf16(acc[mb], Al[1][0], Al[1][1], Al[1][2], Al[1][3], bh2, bh3);
                mma_bf16(acc[mb], Ah[0][0], Ah[0][1], Ah[0][2], Ah[0][3], bl0, bl1);
                mma_bf16(acc[mb], Ah[1][0], Ah[1][1], Ah[1][2], Ah[1][3], bl2, bl3);
            }
        }
        __syncthreads();
    }

    const int nA = n0 + wn * 16 + g, nB = nA + 8;
    #pragma unroll
    for (int mb = 0; mb < 4; mb++) {
        int m = mt * 64 + wm * 32 + mb * 8 + 2 * tg;
        float bv0 = bias ? bias[m] : 0.0f;
        float bv1 = bias ? bias[m + 1] : 0.0f;
        float* o0 = out + ((size_t)b * M + m) * N_;
        float* o1 = o0 + N_;
        o0[nA] = acc[mb][0] + bv0;
        o1[nA] = acc[mb][1] + bv1;
        o0[nB] = acc[mb][2] + bv0;
        o1[nB] = acc[mb][3] + bv1;
    }
}

// ---------------------------------------------------------------------------
// Per (b,hd): q,k row norms (-> folded scale) and v row sum.
// ---------------------------------------------------------------------------
__global__ void __launch_bounds__(256) norm_kernel()
{
    const int idx = blockIdx.x;
    const int b  = idx >> 7;
    const int hd = idx & 127;
    const float* q = g_qkv + ((size_t)(b * OQKV_ + hd)) * N_;
    const float* k = q + (size_t)HID_ * N_;
    const float* v = q + (size_t)(2 * HID_) * N_;

    float sq = 0.f, sk = 0.f, sv = 0.f;
    for (int i = threadIdx.x; i < N_; i += 256) {
        float a = q[i]; sq += a * a;
        float c = k[i]; sk += c * c;
        sv += v[i];
    }
    __shared__ float rq[256], rk[256], rv[256];
    rq[threadIdx.x] = sq; rk[threadIdx.x] = sk; rv[threadIdx.x] = sv;
    __syncthreads();
    for (int s = 128; s > 0; s >>= 1) {
        if (threadIdx.x < s) {
            rq[threadIdx.x] += rq[threadIdx.x + s];
            rk[threadIdx.x] += rk[threadIdx.x + s];
            rv[threadIdx.x] += rv[threadIdx.x + s];
        }
        __syncthreads();
    }
    if (threadIdx.x == 0) {
        float nq = fmaxf(sqrtf(rq[0]), 1e-12f);
        float nk = fmaxf(sqrtf(rk[0]), 1e-12f);
        g_scale[idx] = 10.0f / (nq * nk);
        g_vsum[idx]  = rv[0];
    }
}

// ---------------------------------------------------------------------------
// Pack K' (k * folded scale) and V into bf16 LDSM-ready tiles.
// ---------------------------------------------------------------------------
__global__ void __launch_bounds__(256) pack_kernel()
{
    const int bh = blockIdx.y, ti = blockIdx.x;
    const int b = bh >> 2, h = bh & 3;
    const float* kb = g_qkv + ((size_t)(b * OQKV_) + HID_ + h * DH_) * N_;
    const float* vb = kb + (size_t)HID_ * N_;

    const int j  = threadIdx.x & 63;
    const int dg = threadIdx.x >> 6;
    const int jt = ti * 64;
    unsigned char* out = g_pack + ((size_t)bh * 64 + ti) * TILEB;

    uint32_t kw[4], vw[4];
    #pragma unroll
    for (int p = 0; p < 4; p++) {
        int d = dg * 8 + 2 * p;
        float c0 = g_scale[bh * DH_ + d];
        float c1 = g_scale[bh * DH_ + d + 1];
        float k0 = kb[(size_t)d * N_ + jt + j];
        float k1 = kb[(size_t)(d + 1) * N_ + jt + j];
        kw[p] = packbf2(k0 * c0, k1 * c1);
        vw[p] = packbf2(vb[(size_t)d * N_ + jt + j], vb[(size_t)(d + 1) * N_ + jt + j]);
    }
    *(uint4*)(out + j * TPITCH + dg * 16)        = make_uint4(kw[0], kw[1], kw[2], kw[3]);
    *(uint4*)(out + 5120 + j * TPITCH + dg * 16) = make_uint4(vw[0], vw[1], vw[2], vw[3]);
}

// ---------------------------------------------------------------------------
// bf16 mma.sync flash attention — 128-thread CTAs, warp owns 16 rows,
// 6 CTAs/SM (launch_bounds(128,6), ~60 live regs < 85 cap). 24 warps/SM
// = 6/SMSP: +50% latency cover vs all prior configs — tests the R14 finding
// that the kernel is latency-bound, not tensor-bound. 3-stage pipeline
// (30.7 KB smem) to fit 6 CTAs.
// ---------------------------------------------------------------------------
__global__ void __launch_bounds__(128, 6) attn_mma_kernel()
{
    __shared__ __align__(16) unsigned char sbuf[3][TILEB];  // 30720 B

    const int tid  = threadIdx.x;
    const int lane = tid & 31;
    const int w    = tid >> 5;           // 0..3
    const int g    = lane >> 2;
    const int tg   = lane & 3;

    const int bh = blockIdx.y;
    const int b = bh >> 2, h = bh & 3;
    const int i0 = blockIdx.x * 64 + w * 16;   // warp owns 16 query rows

    const float* qb = g_qkv + ((size_t)(b * OQKV_) + h * DH_) * N_;
    const unsigned char* pk = g_pack + (size_t)bh * 64 * TILEB;

    // Q fragments: 2 k-steps x 4
    uint32_t qa[2][4];
    #pragma unroll
    for (int ks = 0; ks < 2; ks++) {
        #pragma unroll
        for (int rr = 0; rr < 4; rr++) {
            int r = i0 + g + ((rr & 1) ? 8 : 0);
            int d = ks * 16 + 2 * tg + ((rr >> 1) ? 8 : 0);
            qa[ks][rr] = packbf2(qb[(size_t)d * N_ + r], qb[(size_t)(d + 1) * N_ + r]);
        }
    }

    const __nv_bfloat162 C5   = __float2bfloat162_rn(0.5f);
    const __nv_bfloat162 ONE  = __float2bfloat162_rn(1.0f);
    const __nv_bfloat162 ZERO = __float2bfloat162_rn(0.0f);

    auto issue = [&](int ti) {
        const unsigned char* src = pk + (size_t)ti * TILEB;
        uint32_t dst = smem_to_u32(sbuf[ti % 3]);
        #pragma unroll
        for (int c = 0; c < 5; c++)   // 640 chunks / 128 threads = 5 each
            cp_async16(dst + (tid + c * 128) * 16, src + (tid + c * 128) * 16);
        asm volatile("cp.async.commit_group;" ::: "memory");
    };

    float oacc[4][4] = {};
    __nv_bfloat162 ls0 = ZERO, ls1 = ZERO;

    issue(0); issue(1);

    for (int ti = 0; ti < 64; ti++) {
        asm volatile("cp.async.wait_group 1;" ::: "memory");
        __syncthreads();
        if (ti + 2 < 64) issue(ti + 2);   // buf (ti+2)%3 consumed at ti-1, safe post-sync

        const uint32_t smK = smem_to_u32(sbuf[ti % 3]);
        const uint32_t smV = smK + 5120;

        #pragma unroll
        for (int hf = 0; hf < 2; hf++) {
            // S + epilogue per n-block
            uint32_t pa[2][4];   // [pair][frag]
            #pragma unroll
            for (int q4 = 0; q4 < 4; q4++) {
                uint32_t r0, r1, r2, r3;
                uint32_t jrow = (uint32_t)((hf * 4 + q4) * 8 + (lane & 7));
                ldsm4(r0, r1, r2, r3, smK + jrow * TPITCH + (uint32_t)(lane >> 3) * 16u);
                float sc[4];
                mma_bf16_zc(sc, qa[0][0], qa[0][1], qa[0][2], qa[0][3], r0, r1);
                mma_bf16  (sc, qa[1][0], qa[1][1], qa[1][2], qa[1][3], r2, r3);
                // delta = s * (1 + s/2); lsum accumulated on FMA pipe
                __nv_bfloat162 s01 = __floats2bfloat162_rn(sc[0], sc[1]);
                __nv_bfloat162 s23 = __floats2bfloat162_rn(sc[2], sc[3]);
                __nv_bfloat162 t01 = __hfma2(s01, C5, ONE);
                __nv_bfloat162 t23 = __hfma2(s23, C5, ONE);
                __nv_bfloat162 d01 = __hmul2(s01, t01);
                __nv_bfloat162 d23 = __hmul2(s23, t23);
                ls0 = __hadd2(ls0, d01);
                ls1 = __hadd2(ls1, d23);
                pa[q4 >> 1][(q4 & 1) * 2 + 0] = bf2u(d01);
                pa[q4 >> 1][(q4 & 1) * 2 + 1] = bf2u(d23);
            }

            // PV over 4 d-blocks
            #pragma unroll
            for (int nbd = 0; nbd < 4; nbd++) {
                uint32_t v0, v1, v2, v3;
                ldsm4t(v0, v1, v2, v3,
                       smV + (uint32_t)(hf * 32 + lane) * TPITCH + (uint32_t)nbd * 16u);
                mma_bf16(oacc[nbd], pa[0][0], pa[0][1], pa[0][2], pa[0][3], v0, v1);
                mma_bf16(oacc[nbd], pa[1][0], pa[1][1], pa[1][2], pa[1][3], v2, v3);
            }
        }
    }

    // reduce lsum across the 4 tg lanes of each row group
    float lA = __bfloat162float(ls0.x) + __bfloat162float(ls0.y);
    float lB = __bfloat162float(ls1.x) + __bfloat162float(ls1.y);
    lA += __shfl_xor_sync(0xffffffffu, lA, 1);
    lA += __shfl_xor_sync(0xffffffffu, lA, 2);
    lB += __shfl_xor_sync(0xffffffffu, lB, 1);
    lB += __shfl_xor_sync(0xffffffffu, lB, 2);
    const float rA = 1.0f / (4096.0f + lA);
    const float rB = 1.0f / (4096.0f + lB);

    // out = (vsum + OUT) / denom, written as bf16 hi/lo split (channel-major)
    const int chan0 = b * HID_ + h * DH_;
    const int iA = i0 + g, iB = iA + 8;
    #pragma unroll
    for (int nbd = 0; nbd < 4; nbd++) {
        int d0 = nbd * 8 + 2 * tg;
        float vs0 = g_vsum[chan0 + d0];
        float vs1 = g_vsum[chan0 + d0 + 1];
        float o00 = (vs0 + oacc[nbd][0]) * rA;
        float o10 = (vs1 + oacc[nbd][1]) * rA;
        float o01 = (vs0 + oacc[nbd][2]) * rB;
        float o11 = (vs1 + oacc[nbd][3]) * rB;
        size_t p0 = (size_t)(chan0 + d0) * N_;
        size_t p1 = p0 + N_;
        __nv_bfloat16 hh;
        hh = __float2bfloat16_rn(o00); g_oh[p0 + iA] = hh;
        g_ol[p0 + iA] = __float2bfloat16_rn(o00 - __bfloat162float(hh));
        hh = __float2bfloat16_rn(o10); g_oh[p1 + iA] = hh;
        g_ol[p1 + iA] = __float2bfloat16_rn(o10 - __bfloat162float(hh));
        hh = __float2bfloat16_rn(o01); g_oh[p0 + iB] = hh;
        g_ol[p0 + iB] = __float2bfloat16_rn(o01 - __bfloat162float(hh));
        hh = __float2bfloat16_rn(o11); g_oh[p1 + iB] = hh;
        g_ol[p1 + iB] = __float2bfloat16_rn(o11 - __bfloat162float(hh));
    }
}

// ---------------------------------------------------------------------------
extern "C" void kernel_launch(void* const* d_in, const int* in_sizes, int n_in,
                              void* d_out, int out_size)
{
    (void)in_sizes; (void)n_in; (void)out_size;
    const float* x     = (const float*)d_in[0];
    const float* w_qkv = (const float*)d_in[1];
    const float* w_out = (const float*)d_in[2];
    const float* b_out = (const float*)d_in[3];
    float* y = (float*)d_out;

    float *qkv_p;
    __nv_bfloat16 *xh_p, *xl_p, *oh_p, *ol_p;
    unsigned char *wp1_p, *wp2_p;
    cudaGetSymbolAddress((void**)&qkv_p,  g_qkv);
    cudaGetSymbolAddress((void**)&xh_p,   g_xh);
    cudaGetSymbolAddress((void**)&xl_p,   g_xl);
    cudaGetSymbolAddress((void**)&oh_p,   g_oh);
    cudaGetSymbolAddress((void**)&ol_p,   g_ol);
    cudaGetSymbolAddress((void**)&wp1_p,  g_wp1);
    cudaGetSymbolAddress((void**)&wp2_p,  g_wp2);

    // split-convert inputs once
    convert_split<<<(B_ * CIN_ * N_) / 1024, 256>>>(x, xh_p, xl_p, (B_ * CIN_ * N_) / 4);
    convert_w<<<dim3(OQKV_ / 64, CIN_ / 32), 256>>>(w_qkv, wp1_p, OQKV_, CIN_);
    convert_w<<<dim3(CIN_ / 64, HID_ / 32), 256>>>(w_out, wp2_p, CIN_, HID_);

    // 1) QKV projection: q/k m-tiles (0..3) single-pass bf16, v tiles (4,5) 3-pass
    gemm_mma<<<dim3(N_ / 64, OQKV_ / 64, B_), 256>>>(xh_p, xl_p, wp1_p, nullptr,
                                                     qkv_p, OQKV_, CIN_, 4);
    // 2) norms + folded scale, 3) bf16 tile pack, 4) attention (writes oh/ol)
    norm_kernel<<<B_ * HID_, 256>>>();
    pack_kernel<<<dim3(64, 16), 256>>>();
    attn_mma_kernel<<<dim3(N_ / 64, B_ * HEADS_), 128>>>();

    // 5) output projection on tensor cores (all tiles 3-pass)
    gemm_mma<<<dim3(N_ / 64, CIN_ / 64, B_), 256>>>(oh_p, ol_p, wp2_p, b_out,
                                                    y, CIN_, HID_, 0);
}

// round 16
// speedup vs baseline: 1.1660x; 1.0002x over previous
#include <cuda_runtime.h>
#include <cuda_fp16.h>
#include <math.h>
#include <cstdint>

#define B_     4
#define CIN_   256
#define N_     4096
#define HEADS_ 4
#define DH_    32
#define HID_   128
#define OQKV_  384
#define TPITCH 80u
#define TILEB  10240

// Scratch (allocation-free rule: __device__ globals)
__device__ float g_qkv[B_ * OQKV_ * N_];    // [b][o][n]: q 0..127, k 128..255, v 256..383
__device__ float g_scale[B_ * HID_];        // 10 / (||q_d|| ||k_d||)
__device__ float g_vsum[B_ * HID_];         // sum_j v[d][j]
__device__ __align__(16) unsigned char g_pack[16 * 64 * TILEB];  // attn K'/V fp16 tiles
// fp16 operands for the projection GEMMs
__device__ __align__(16) __half g_xh[B_ * CIN_ * N_];            // x (single-pass suffices)
__device__ __align__(16) __half g_oh[B_ * HID_ * N_];            // attn out hi
__device__ __align__(16) __half g_ol[B_ * HID_ * N_];            // attn out lo (fp16 residual)
// W hi/lo packed into cp.async-ready 64m x 32k tiles (80B pitch rows, hi|lo)
__device__ __align__(16) unsigned char g_wp1[6 * 8 * TILEB];     // w_qkv: 384x256
__device__ __align__(16) unsigned char g_wp2[4 * 4 * TILEB];     // w_out: 256x128

// ---------------------------------------------------------------------------
// helpers
// ---------------------------------------------------------------------------
__device__ __forceinline__ uint32_t smem_to_u32(const void* p) {
    uint32_t a;
    asm("{ .reg .u64 t; cvta.to.shared.u64 t, %1; cvt.u32.u64 %0, t; }" : "=r"(a) : "l"(p));
    return a;
}

__device__ __forceinline__ void mma_f16(float c[4],
                                        uint32_t a0, uint32_t a1, uint32_t a2, uint32_t a3,
                                        uint32_t b0, uint32_t b1) {
    asm volatile(
        "mma.sync.aligned.m16n8k16.row.col.f32.f16.f16.f32 "
        "{%0,%1,%2,%3}, {%4,%5,%6,%7}, {%8,%9}, {%0,%1,%2,%3};"
        : "+f"(c[0]), "+f"(c[1]), "+f"(c[2]), "+f"(c[3])
        : "r"(a0), "r"(a1), "r"(a2), "r"(a3), "r"(b0), "r"(b1));
}

// D = A.B + 0 : separate D/C, C = hoisted zero regs
__device__ __forceinline__ void mma_f16_zc(float c[4],
                                           uint32_t a0, uint32_t a1, uint32_t a2, uint32_t a3,
                                           uint32_t b0, uint32_t b1) {
    asm volatile(
        "mma.sync.aligned.m16n8k16.row.col.f32.f16.f16.f32 "
        "{%0,%1,%2,%3}, {%4,%5,%6,%7}, {%8,%9}, {%10,%11,%12,%13};"
        : "=f"(c[0]), "=f"(c[1]), "=f"(c[2]), "=f"(c[3])
        : "r"(a0), "r"(a1), "r"(a2), "r"(a3), "r"(b0), "r"(b1),
          "f"(0.0f), "f"(0.0f), "f"(0.0f), "f"(0.0f));
}

__device__ __forceinline__ void ldsm4(uint32_t& r0, uint32_t& r1, uint32_t& r2, uint32_t& r3,
                                      uint32_t addr) {
    asm volatile("ldmatrix.sync.aligned.m8n8.x4.shared.b16 {%0,%1,%2,%3}, [%4];"
                 : "=r"(r0), "=r"(r1), "=r"(r2), "=r"(r3) : "r"(addr));
}
__device__ __forceinline__ void ldsm4t(uint32_t& r0, uint32_t& r1, uint32_t& r2, uint32_t& r3,
                                       uint32_t addr) {
    asm volatile("ldmatrix.sync.aligned.m8n8.x4.trans.shared.b16 {%0,%1,%2,%3}, [%4];"
                 : "=r"(r0), "=r"(r1), "=r"(r2), "=r"(r3) : "r"(addr));
}

__device__ __forceinline__ uint32_t packh2(float lo, float hi) {
    __half2 p = __floats2half2_rn(lo, hi);
    return *reinterpret_cast<uint32_t*>(&p);
}
__device__ __forceinline__ uint32_t h2u(__half2 p) {
    return *reinterpret_cast<uint32_t*>(&p);
}

__device__ __forceinline__ void cp_async16(uint32_t s, const void* g) {
    asm volatile("cp.async.cg.shared.global [%0], [%1], 16;" :: "r"(s), "l"(g));
}

// ---------------------------------------------------------------------------
// convert_h: fp32 -> fp16, 4 elems/thread (single-pass operand for qkv gemm)
// ---------------------------------------------------------------------------
__global__ void __launch_bounds__(256) convert_h(
    const float* __restrict__ src, __half* __restrict__ dst, int n4)
{
    int idx = blockIdx.x * 256 + threadIdx.x;
    if (idx >= n4) return;
    float4 f = reinterpret_cast<const float4*>(src)[idx];
    uint2 hw;
    hw.x = packh2(f.x, f.y);
    hw.y = packh2(f.z, f.w);
    reinterpret_cast<uint2*>(dst)[idx] = hw;
}

// ---------------------------------------------------------------------------
// convert_w: W fp32 [M][K] -> packed fp16 tiles [mt][s][hi 64x80B | lo 64x80B]
// ---------------------------------------------------------------------------
__global__ void __launch_bounds__(256) convert_w(
    const float* __restrict__ W, unsigned char* __restrict__ dst, int M, int K)
{
    const int mt = blockIdx.x, s = blockIdx.y;
    const int m  = threadIdx.x & 63;
    const int kg = (threadIdx.x >> 6) * 8;
    unsigned char* base = dst + ((size_t)mt * (K >> 5) + s) * TILEB;
    const float* wrow = W + (size_t)(mt * 64 + m) * K + s * 32 + kg;

    #pragma unroll
    for (int p = 0; p < 4; p++) {
        float w0 = wrow[2 * p], w1 = wrow[2 * p + 1];
        __half h0 = __float2half_rn(w0);
        __half h1 = __float2half_rn(w1);
        __half2 ph; ph.x = h0; ph.y = h1;
        int k = kg + 2 * p;
        uint32_t off = (uint32_t)m * TPITCH + (uint32_t)((k >> 3) * 16 + (k & 7) * 2);
        *reinterpret_cast<uint32_t*>(base + off) = h2u(ph);
        *reinterpret_cast<uint32_t*>(base + 5120 + off) =
            packh2(w0 - __half2float(h0), w1 - __half2float(h1));
    }
}

// ---------------------------------------------------------------------------
// Split-fp16 tensor-core GEMM: out[b][m][n] = sum_k W[m][k] X[b][k][n] (+bias)
// m-tiles >= mt3: 3-pass (Xh.Wh + Xl.Wh + Xh.Wl). m-tiles < mt3: single-pass
// (fp16's 11-bit mantissa -> ~4e-4 rel err, fine for q/k/v pre-attention).
// ---------------------------------------------------------------------------
__global__ void __launch_bounds__(256) gemm_mma(
    const __half* __restrict__ Xh, const __half* __restrict__ Xl,
    const unsigned char* __restrict__ Wp, const float* __restrict__ bias,
    float* __restrict__ out, int M, int K, int mt3)
{
    __shared__ __align__(16) unsigned char smem[2][18432];

    const int tid = threadIdx.x, lane = tid & 31, w = tid >> 5;
    const int wn = w & 3, wm = w >> 2;
    const int g = lane >> 2, tg = lane & 3;
    const int n0 = blockIdx.x * 64, mt = blockIdx.y, b = blockIdx.z;
    const int nstages = K >> 5;
    const bool full = (mt >= mt3);

    const __half* xh = Xh + (size_t)b * K * N_ + n0;
    const __half* xl = Xl + (size_t)b * K * N_ + n0;
    const unsigned char* wp = Wp + (size_t)mt * nstages * TILEB;

    const int ck = tid >> 3, cc = tid & 7;
    const uint32_t xdst = (uint32_t)(ck * 128 + ((cc ^ (ck & 7)) * 16));

    auto issue = [&](int s) {
        uint32_t dst = smem_to_u32(smem[s & 1]);
        const char* sh = (const char*)(xh + (size_t)(s * 32 + ck) * N_) + cc * 16;
        cp_async16(dst + xdst, sh);
        if (full) {
            const char* sl = (const char*)(xl + (size_t)(s * 32 + ck) * N_) + cc * 16;
            cp_async16(dst + 4096 + xdst, sl);
        }
        const unsigned char* ws = wp + (size_t)s * TILEB;
        cp_async16(dst + 8192 + tid * 16, ws + tid * 16);
        cp_async16(dst + 8192 + (tid + 256) * 16, ws + (tid + 256) * 16);
        if (full && tid < 128)
            cp_async16(dst + 8192 + (tid + 512) * 16, ws + (tid + 512) * 16);
        asm volatile("cp.async.commit_group;" ::: "memory");
    };

    float acc[4][4] = {};

    issue(0);
    for (int s = 0; s < nstages; s++) {
        if (s + 1 < nstages) {
            issue(s + 1);
            asm volatile("cp.async.wait_group 1;" ::: "memory");
        } else {
            asm volatile("cp.async.wait_group 0;" ::: "memory");
        }
        __syncthreads();

        const uint32_t smX = smem_to_u32(smem[s & 1]);
        const uint32_t smW = smX + 8192;

        uint32_t Ah[2][4], Al[2][4];
        const int arow = ((lane & 16) >> 1) + (lane & 7);
        const int alog = wn * 2 + ((lane >> 3) & 1);
        #pragma unroll
        for (int ks = 0; ks < 2; ks++) {
            int kr = ks * 16 + arow;
            uint32_t aoff = (uint32_t)(kr * 128 + ((alog ^ (kr & 7)) * 16));
            ldsm4t(Ah[ks][0], Ah[ks][1], Ah[ks][2], Ah[ks][3], smX + aoff);
            if (full)
                ldsm4t(Al[ks][0], Al[ks][1], Al[ks][2], Al[ks][3], smX + 4096 + aoff);
        }

        #pragma unroll
        for (int mb = 0; mb < 4; mb++) {
            uint32_t waddr = smW + (uint32_t)((wm * 32 + mb * 8 + (lane & 7)) * TPITCH
                                              + (lane >> 3) * 16);
            uint32_t bh0, bh1, bh2, bh3;
            ldsm4(bh0, bh1, bh2, bh3, waddr);
            mma_f16(acc[mb], Ah[0][0], Ah[0][1], Ah[0][2], Ah[0][3], bh0, bh1);
            mma_f16(acc[mb], Ah[1][0], Ah[1][1], Ah[1][2], Ah[1][3], bh2, bh3);
            if (full) {
                uint32_t bl0, bl1, bl2, bl3;
                ldsm4(bl0, bl1, bl2, bl3, waddr + 5120);
                mma_f16(acc[mb], Al[0][0], Al[0][1], Al[0][2], Al[0][3], bh0, bh1);
                mma_f16(acc[mb], Al[1][0], Al[1][1], Al[1][2], Al[1][3], bh2, bh3);
                mma_f16(acc[mb], Ah[0][0], Ah[0][1], Ah[0][2], Ah[0][3], bl0, bl1);
                mma_f16(acc[mb], Ah[1][0], Ah[1][1], Ah[1][2], Ah[1][3], bl2, bl3);
            }
        }
        __syncthreads();
    }

    const int nA = n0 + wn * 16 + g, nB = nA + 8;
    #pragma unroll
    for (int mb = 0; mb < 4; mb++) {
        int m = mt * 64 + wm * 32 + mb * 8 + 2 * tg;
        float bv0 = bias ? bias[m] : 0.0f;
        float bv1 = bias ? bias[m + 1] : 0.0f;
        float* o0 = out + ((size_t)b * M + m) * N_;
        float* o1 = o0 + N_;
        o0[nA] = acc[mb][0] + bv0;
        o1[nA] = acc[mb][1] + bv1;
        o0[nB] = acc[mb][2] + bv0;
        o1[nB] = acc[mb][3] + bv1;
    }
}

// ---------------------------------------------------------------------------
// Per (b,hd): q,k row norms (-> folded scale) and v row sum.
// ---------------------------------------------------------------------------
__global__ void __launch_bounds__(256) norm_kernel()
{
    const int idx = blockIdx.x;
    const int b  = idx >> 7;
    const int hd = idx & 127;
    const float* q = g_qkv + ((size_t)(b * OQKV_ + hd)) * N_;
    const float* k = q + (size_t)HID_ * N_;
    const float* v = q + (size_t)(2 * HID_) * N_;

    float sq = 0.f, sk = 0.f, sv = 0.f;
    for (int i = threadIdx.x; i < N_; i += 256) {
        float a = q[i]; sq += a * a;
        float c = k[i]; sk += c * c;
        sv += v[i];
    }
    __shared__ float rq[256], rk[256], rv[256];
    rq[threadIdx.x] = sq; rk[threadIdx.x] = sk; rv[threadIdx.x] = sv;
    __syncthreads();
    for (int s = 128; s > 0; s >>= 1) {
        if (threadIdx.x < s) {
            rq[threadIdx.x] += rq[threadIdx.x + s];
            rk[threadIdx.x] += rk[threadIdx.x + s];
            rv[threadIdx.x] += rv[threadIdx.x + s];
        }
        __syncthreads();
    }
    if (threadIdx.x == 0) {
        float nq = fmaxf(sqrtf(rq[0]), 1e-12f);
        float nk = fmaxf(sqrtf(rk[0]), 1e-12f);
        g_scale[idx] = 10.0f / (nq * nk);
        g_vsum[idx]  = rv[0];
    }
}

// ---------------------------------------------------------------------------
// Pack K' (k * folded scale) and V into fp16 LDSM-ready tiles.
// ---------------------------------------------------------------------------
__global__ void __launch_bounds__(256) pack_kernel()
{
    const int bh = blockIdx.y, ti = blockIdx.x;
    const int b = bh >> 2, h = bh & 3;
    const float* kb = g_qkv + ((size_t)(b * OQKV_) + HID_ + h * DH_) * N_;
    const float* vb = kb + (size_t)HID_ * N_;

    const int j  = threadIdx.x & 63;
    const int dg = threadIdx.x >> 6;
    const int jt = ti * 64;
    unsigned char* out = g_pack + ((size_t)bh * 64 + ti) * TILEB;

    uint32_t kw[4], vw[4];
    #pragma unroll
    for (int p = 0; p < 4; p++) {
        int d = dg * 8 + 2 * p;
        float c0 = g_scale[bh * DH_ + d];
        float c1 = g_scale[bh * DH_ + d + 1];
        float k0 = kb[(size_t)d * N_ + jt + j];
        float k1 = kb[(size_t)(d + 1) * N_ + jt + j];
        kw[p] = packh2(k0 * c0, k1 * c1);
        vw[p] = packh2(vb[(size_t)d * N_ + jt + j], vb[(size_t)(d + 1) * N_ + jt + j]);
    }
    *(uint4*)(out + j * TPITCH + dg * 16)        = make_uint4(kw[0], kw[1], kw[2], kw[3]);
    *(uint4*)(out + 5120 + j * TPITCH + dg * 16) = make_uint4(vw[0], vw[1], vw[2], vw[3]);
}

// ---------------------------------------------------------------------------
// fp16 mma.sync flash attention — R15 shape (128 thr, warp owns 16 rows,
// 6 CTAs/SM, 3-stage pipeline), all operand math in __half2. fp16 P rounding
// is 8x finer than bf16 (11-bit mantissa).
// ---------------------------------------------------------------------------
__global__ void __launch_bounds__(128, 6) attn_mma_kernel()
{
    __shared__ __align__(16) unsigned char sbuf[3][TILEB];  // 30720 B

    const int tid  = threadIdx.x;
    const int lane = tid & 31;
    const int w    = tid >> 5;           // 0..3
    const int g    = lane >> 2;
    const int tg   = lane & 3;

    const int bh = blockIdx.y;
    const int b = bh >> 2, h = bh & 3;
    const int i0 = blockIdx.x * 64 + w * 16;   // warp owns 16 query rows

    const float* qb = g_qkv + ((size_t)(b * OQKV_) + h * DH_) * N_;
    const unsigned char* pk = g_pack + (size_t)bh * 64 * TILEB;

    // Q fragments: 2 k-steps x 4
    uint32_t qa[2][4];
    #pragma unroll
    for (int ks = 0; ks < 2; ks++) {
        #pragma unroll
        for (int rr = 0; rr < 4; rr++) {
            int r = i0 + g + ((rr & 1) ? 8 : 0);
            int d = ks * 16 + 2 * tg + ((rr >> 1) ? 8 : 0);
            qa[ks][rr] = packh2(qb[(size_t)d * N_ + r], qb[(size_t)(d + 1) * N_ + r]);
        }
    }

    const __half2 C5   = __float2half2_rn(0.5f);
    const __half2 ONE  = __float2half2_rn(1.0f);
    const __half2 ZERO = __float2half2_rn(0.0f);

    auto issue = [&](int ti) {
        const unsigned char* src = pk + (size_t)ti * TILEB;
        uint32_t dst = smem_to_u32(sbuf[ti % 3]);
        #pragma unroll
        for (int c = 0; c < 5; c++)   // 640 chunks / 128 threads = 5 each
            cp_async16(dst + (tid + c * 128) * 16, src + (tid + c * 128) * 16);
        asm volatile("cp.async.commit_group;" ::: "memory");
    };

    float oacc[4][4] = {};
    __half2 ls0 = ZERO, ls1 = ZERO;

    issue(0); issue(1);

    for (int ti = 0; ti < 64; ti++) {
        asm volatile("cp.async.wait_group 1;" ::: "memory");
        __syncthreads();
        if (ti + 2 < 64) issue(ti + 2);   // buf (ti+2)%3 consumed at ti-1, safe post-sync

        const uint32_t smK = smem_to_u32(sbuf[ti % 3]);
        const uint32_t smV = smK + 5120;

        #pragma unroll
        for (int hf = 0; hf < 2; hf++) {
            // S + epilogue per n-block
            uint32_t pa[2][4];   // [pair][frag]
            #pragma unroll
            for (int q4 = 0; q4 < 4; q4++) {
                uint32_t r0, r1, r2, r3;
                uint32_t jrow = (uint32_t)((hf * 4 + q4) * 8 + (lane & 7));
                ldsm4(r0, r1, r2, r3, smK + jrow * TPITCH + (uint32_t)(lane >> 3) * 16u);
                float sc[4];
                mma_f16_zc(sc, qa[0][0], qa[0][1], qa[0][2], qa[0][3], r0, r1);
                mma_f16  (sc, qa[1][0], qa[1][1], qa[1][2], qa[1][3], r2, r3);
                // delta = s * (1 + s/2); lsum accumulated on FMA pipe
                __half2 s01 = __floats2half2_rn(sc[0], sc[1]);
                __half2 s23 = __floats2half2_rn(sc[2], sc[3]);
                __half2 t01 = __hfma2(s01, C5, ONE);
                __half2 t23 = __hfma2(s23, C5, ONE);
                __half2 d01 = __hmul2(s01, t01);
                __half2 d23 = __hmul2(s23, t23);
                ls0 = __hadd2(ls0, d01);
                ls1 = __hadd2(ls1, d23);
                pa[q4 >> 1][(q4 & 1) * 2 + 0] = h2u(d01);
                pa[q4 >> 1][(q4 & 1) * 2 + 1] = h2u(d23);
            }

            // PV over 4 d-blocks
            #pragma unroll
            for (int nbd = 0; nbd < 4; nbd++) {
                uint32_t v0, v1, v2, v3;
                ldsm4t(v0, v1, v2, v3,
                       smV + (uint32_t)(hf * 32 + lane) * TPITCH + (uint32_t)nbd * 16u);
                mma_f16(oacc[nbd], pa[0][0], pa[0][1], pa[0][2], pa[0][3], v0, v1);
                mma_f16(oacc[nbd], pa[1][0], pa[1][1], pa[1][2], pa[1][3], v2, v3);
            }
        }
    }

    // reduce lsum across the 4 tg lanes of each row group
    float lA = __half2float(ls0.x) + __half2float(ls0.y);
    float lB = __half2float(ls1.x) + __half2float(ls1.y);
    lA += __shfl_xor_sync(0xffffffffu, lA, 1);
    lA += __shfl_xor_sync(0xffffffffu, lA, 2);
    lB += __shfl_xor_sync(0xffffffffu, lB, 1);
    lB += __shfl_xor_sync(0xffffffffu, lB, 2);
    const float rA = 1.0f / (4096.0f + lA);
    const float rB = 1.0f / (4096.0f + lB);

    // out = (vsum + OUT) / denom, written as fp16 hi/lo split (channel-major)
    const int chan0 = b * HID_ + h * DH_;
    const int iA = i0 + g, iB = iA + 8;
    #pragma unroll
    for (int nbd = 0; nbd < 4; nbd++) {
        int d0 = nbd * 8 + 2 * tg;
        float vs0 = g_vsum[chan0 + d0];
        float vs1 = g_vsum[chan0 + d0 + 1];
        float o00 = (vs0 + oacc[nbd][0]) * rA;
        float o10 = (vs1 + oacc[nbd][1]) * rA;
        float o01 = (vs0 + oacc[nbd][2]) * rB;
        float o11 = (vs1 + oacc[nbd][3]) * rB;
        size_t p0 = (size_t)(chan0 + d0) * N_;
        size_t p1 = p0 + N_;
        __half hh;
        hh = __float2half_rn(o00); g_oh[p0 + iA] = hh;
        g_ol[p0 + iA] = __float2half_rn(o00 - __half2float(hh));
        hh = __float2half_rn(o10); g_oh[p1 + iA] = hh;
        g_ol[p1 + iA] = __float2half_rn(o10 - __half2float(hh));
        hh = __float2half_rn(o01); g_oh[p0 + iB] = hh;
        g_ol[p0 + iB] = __float2half_rn(o01 - __half2float(hh));
        hh = __float2half_rn(o11); g_oh[p1 + iB] = hh;
        g_ol[p1 + iB] = __float2half_rn(o11 - __half2float(hh));
    }
}

// ---------------------------------------------------------------------------
extern "C" void kernel_launch(void* const* d_in, const int* in_sizes, int n_in,
                              void* d_out, int out_size)
{
    (void)in_sizes; (void)n_in; (void)out_size;
    const float* x     = (const float*)d_in[0];
    const float* w_qkv = (const float*)d_in[1];
    const float* w_out = (const float*)d_in[2];
    const float* b_out = (const float*)d_in[3];
    float* y = (float*)d_out;

    float *qkv_p;
    __half *xh_p, *oh_p, *ol_p;
    unsigned char *wp1_p, *wp2_p;
    cudaGetSymbolAddress((void**)&qkv_p,  g_qkv);
    cudaGetSymbolAddress((void**)&xh_p,   g_xh);
    cudaGetSymbolAddress((void**)&oh_p,   g_oh);
    cudaGetSymbolAddress((void**)&ol_p,   g_ol);
    cudaGetSymbolAddress((void**)&wp1_p,  g_wp1);
    cudaGetSymbolAddress((void**)&wp2_p,  g_wp2);

    // convert inputs once (x single fp16; W hi/lo fp16)
    convert_h<<<(B_ * CIN_ * N_) / 1024, 256>>>(x, xh_p, (B_ * CIN_ * N_) / 4);
    convert_w<<<dim3(OQKV_ / 64, CIN_ / 32), 256>>>(w_qkv, wp1_p, OQKV_, CIN_);
    convert_w<<<dim3(CIN_ / 64, HID_ / 32), 256>>>(w_out, wp2_p, CIN_, HID_);

    // 1) QKV projection: ALL m-tiles single-pass fp16 (mt3 = 6)
    gemm_mma<<<dim3(N_ / 64, OQKV_ / 64, B_), 256>>>(xh_p, xh_p, wp1_p, nullptr,
                                                     qkv_p, OQKV_, CIN_, 6);
    // 2) norms + folded scale, 3) fp16 tile pack, 4) attention (writes oh/ol)
    norm_kernel<<<B_ * HID_, 256>>>();
    pack_kernel<<<dim3(64, 16), 256>>>();
    attn_mma_kernel<<<dim3(N_ / 64, B_ * HEADS_), 128>>>();

    // 5) output projection: 3-pass fp16 (protect final precision)
    gemm_mma<<<dim3(N_ / 64, CIN_ / 64, B_), 256>>>(oh_p, ol_p, wp2_p, b_out,
                                                    y, CIN_, HID_, 0);
}